// round 8
// baseline (speedup 1.0000x reference)
#include <cuda_runtime.h>
#include <math.h>
#include <stdint.h>

// ---------------- problem constants ----------------
constexpr int cB   = 2;
constexpr int cL   = 1024;
constexpr int cD   = 1024;
constexpr int cDI  = 2048;
constexpr int cDS  = 16;
constexpr int cDTR = 64;
constexpr int cHR  = 16;
constexpr int cDHR = 64;
constexpr int cHA  = 32;
constexpr int cDHA = 32;
constexpr int cNM  = 6;
constexpr int cNR  = 4;
constexpr int cNT  = 2;
constexpr int cBL  = cB * cL;                 // 2048
constexpr int cXDB = cDTR + 2 * cDS;          // 96
constexpr int cWXS = 16;                      // split-K factor for Wx GEMM
constexpr int cU   = 8;                       // mamba scan time-unroll

// ---------------- scratch (no allocations allowed) ----------------
__device__ float g_mx[cBL * cD];
__device__ float g_rx[cBL * cD];
__device__ float g_tx[cBL * cD];
__device__ float g_xn[cBL * cD];
__device__ float g_xz[cBL * 2 * cDI];
__device__ float g_xc[cBL * cDI];
__device__ float g_xdbl[cBL * cXDB];
__device__ float g_wxp[cWXS * cBL * cXDB];
__device__ float g_delta[cBL * cDI];
__device__ float g_ym[cBL * cDI];
__device__ float g_ar[cBL * cD];
__device__ float g_ak[cBL * cD];
__device__ float g_av[cBL * cD];
__device__ float g_br[cBL * cD];
__device__ float g_bk[cBL * cD];
__device__ float g_bv[cBL * cD];
__device__ float g_y1[cBL * cD];
__device__ float g_tq[cBL * cD];
__device__ float g_tk[cBL * cD];
__device__ float g_tv[cBL * cD];
__device__ float g_to[cBL * cD];

// ---------------- helpers ----------------
__device__ __forceinline__ float sigmoid_f(float x) { return 1.f / (1.f + __expf(-x)); }

__device__ __forceinline__ float block_sum256(float v, float* sm) {
    __syncthreads();
    #pragma unroll
    for (int mk = 16; mk; mk >>= 1) v += __shfl_xor_sync(0xffffffffu, v, mk);
    int w = threadIdx.x >> 5;
    if ((threadIdx.x & 31) == 0) sm[w] = v;
    __syncthreads();
    if (threadIdx.x == 0) {
        float t = 0.f;
        #pragma unroll
        for (int i = 0; i < 8; i++) t += sm[i];
        sm[0] = t;
    }
    __syncthreads();
    return sm[0];
}

__device__ __forceinline__ void tf32_split(float v, float& hi, float& lo) {
    uint32_t h;
    asm("cvt.rna.tf32.f32 %0, %1;" : "=r"(h) : "f"(v));
    hi = __uint_as_float(h);
    float d = v - hi;
    uint32_t l;
    asm("cvt.rna.tf32.f32 %0, %1;" : "=r"(l) : "f"(d));
    lo = __uint_as_float(l);
}

__device__ __forceinline__ void mma8(float* c,
                                     uint32_t a0, uint32_t a1, uint32_t a2, uint32_t a3,
                                     uint32_t b0, uint32_t b1)
{
    asm volatile("mma.sync.aligned.m16n8k8.row.col.f32.tf32.tf32.f32 "
                 "{%0,%1,%2,%3}, {%4,%5,%6,%7}, {%8,%9}, {%0,%1,%2,%3};"
                 : "+f"(c[0]), "+f"(c[1]), "+f"(c[2]), "+f"(c[3])
                 : "r"(a0), "r"(a1), "r"(a2), "r"(a3), "r"(b0), "r"(b1));
}

// ---------------- TF32x3 tensor-core GEMM: C[M,N] = epi(A[M,K] @ B[K,N]) ----------------
// hi/lo interleaved float2 smem: one 64-bit LDS fetches both splits of an element.
// A2[m][k] stride 20 float2, B2[k][n] stride 132 float2 (conflict-free per 16-lane phase).
// EPI: 0 none, 1 +bias, 2 softplus(x+bias), 3 +res.
template <int EPI>
__global__ __launch_bounds__(256)
void tgemm_k(int M, int N, int K,
             const float* __restrict__ A, int lda,
             const float* __restrict__ B, int ldb,
             float* __restrict__ C, int ldc,
             const float* __restrict__ bias,
             const float* __restrict__ res)
{
    constexpr int AKP = 20;    // A smem row stride in float2 (16 + 4 pad)
    constexpr int BNP = 132;   // B smem row stride in float2 (128 + 4 pad)
    __shared__ float2 As2[128][AKP];   // [m][k] -> (hi, lo)
    __shared__ float2 Bs2[16][BNP];    // [k][n] -> (hi, lo)

    const int tid  = threadIdx.x;
    const int bm   = blockIdx.y * 128;
    const int bn   = blockIdx.x * 128;
    const int lane = tid & 31, warp = tid >> 5;
    const int wm = (warp >> 1) * 32;
    const int wn = (warp & 1) * 64;
    const int g  = lane >> 2, tg = lane & 3;

    const int ar = tid >> 2, ak = (tid & 3) * 4;     // A: rows ar, ar+64; cols ak..ak+3
    const int br = tid >> 5, bc = (tid & 31) * 4;    // B: rows br, br+8;  cols bc..bc+3

    float acc[2][8][4];
    #pragma unroll
    for (int im = 0; im < 2; im++)
        #pragma unroll
        for (int jn = 0; jn < 8; jn++)
            #pragma unroll
            for (int q = 0; q < 4; q++) acc[im][jn][q] = 0.f;

    const float* Ap = A + (size_t)bm * lda;
    const float* Bp = B + bn;

    float4 Areg0, Areg1, Breg0, Breg1;

    auto gload = [&](int kt) {
        int k0 = kt * 16;
        Areg0 = *(const float4*)(Ap + (size_t)ar * lda + k0 + ak);
        Areg1 = *(const float4*)(Ap + (size_t)(ar + 64) * lda + k0 + ak);
        Breg0 = *(const float4*)(Bp + (size_t)(k0 + br) * ldb + bc);
        Breg1 = *(const float4*)(Bp + (size_t)(k0 + br + 8) * ldb + bc);
    };
    // split a float4 into two float4s of interleaved (hi,lo) pairs
    auto cvt4 = [](float4 v, float4& o01, float4& o23) {
        float h0, l0, h1, l1, h2, l2, h3, l3;
        tf32_split(v.x, h0, l0);
        tf32_split(v.y, h1, l1);
        tf32_split(v.z, h2, l2);
        tf32_split(v.w, h3, l3);
        o01 = make_float4(h0, l0, h1, l1);
        o23 = make_float4(h2, l2, h3, l3);
    };
    auto sstore = [&]() {
        float4 o01, o23;
        cvt4(Areg0, o01, o23);
        *(float4*)&As2[ar][ak]          = o01;
        *(float4*)&As2[ar][ak + 2]      = o23;
        cvt4(Areg1, o01, o23);
        *(float4*)&As2[ar + 64][ak]     = o01;
        *(float4*)&As2[ar + 64][ak + 2] = o23;
        cvt4(Breg0, o01, o23);
        *(float4*)&Bs2[br][bc]          = o01;
        *(float4*)&Bs2[br][bc + 2]      = o23;
        cvt4(Breg1, o01, o23);
        *(float4*)&Bs2[br + 8][bc]      = o01;
        *(float4*)&Bs2[br + 8][bc + 2]  = o23;
    };

    gload(0);
    sstore();
    __syncthreads();

    const int nkt = K / 16;
    for (int kt = 0; kt < nkt; kt++) {
        const bool has_next = (kt + 1 < nkt);
        if (has_next) gload(kt + 1);

        #pragma unroll
        for (int ks = 0; ks < 2; ks++) {
            const int kb = ks * 8;
            uint32_t ahf[2][4], alf[2][4];
            #pragma unroll
            for (int im = 0; im < 2; im++) {
                int m = wm + im * 16 + g;
                float2 x0 = As2[m][kb + tg];
                float2 x1 = As2[m + 8][kb + tg];
                float2 x2 = As2[m][kb + tg + 4];
                float2 x3 = As2[m + 8][kb + tg + 4];
                ahf[im][0] = __float_as_uint(x0.x);
                ahf[im][1] = __float_as_uint(x1.x);
                ahf[im][2] = __float_as_uint(x2.x);
                ahf[im][3] = __float_as_uint(x3.x);
                alf[im][0] = __float_as_uint(x0.y);
                alf[im][1] = __float_as_uint(x1.y);
                alf[im][2] = __float_as_uint(x2.y);
                alf[im][3] = __float_as_uint(x3.y);
            }
            #pragma unroll
            for (int jn = 0; jn < 8; jn++) {
                int n = wn + jn * 8 + g;
                float2 b0 = Bs2[kb + tg][n];
                float2 b1 = Bs2[kb + tg + 4][n];
                uint32_t bh0 = __float_as_uint(b0.x);
                uint32_t bl0 = __float_as_uint(b0.y);
                uint32_t bh1 = __float_as_uint(b1.x);
                uint32_t bl1 = __float_as_uint(b1.y);
                #pragma unroll
                for (int im = 0; im < 2; im++) {
                    mma8(acc[im][jn], ahf[im][0], ahf[im][1], ahf[im][2], ahf[im][3], bl0, bl1);
                    mma8(acc[im][jn], alf[im][0], alf[im][1], alf[im][2], alf[im][3], bh0, bh1);
                    mma8(acc[im][jn], ahf[im][0], ahf[im][1], ahf[im][2], ahf[im][3], bh0, bh1);
                }
            }
        }

        if (has_next) {
            __syncthreads();
            sstore();
            __syncthreads();
        }
    }

    #pragma unroll
    for (int im = 0; im < 2; im++) {
        int r0 = bm + wm + im * 16 + g;
        #pragma unroll
        for (int jn = 0; jn < 8; jn++) {
            int c0 = bn + wn + jn * 8 + 2 * tg;
            float v00 = acc[im][jn][0], v01 = acc[im][jn][1];
            float v10 = acc[im][jn][2], v11 = acc[im][jn][3];
            if (EPI == 1 || EPI == 2) {
                float b0 = bias[c0], b1 = bias[c0 + 1];
                v00 += b0; v01 += b1; v10 += b0; v11 += b1;
            }
            if (EPI == 2) {
                v00 = (v00 > 15.f) ? v00 : log1pf(__expf(v00));
                v01 = (v01 > 15.f) ? v01 : log1pf(__expf(v01));
                v10 = (v10 > 15.f) ? v10 : log1pf(__expf(v10));
                v11 = (v11 > 15.f) ? v11 : log1pf(__expf(v11));
            }
            if (EPI == 3) {
                float2 rA = *(const float2*)(res + (size_t)r0 * ldc + c0);
                float2 rB = *(const float2*)(res + (size_t)(r0 + 8) * ldc + c0);
                v00 += rA.x; v01 += rA.y; v10 += rB.x; v11 += rB.y;
            }
            float2 o0 = make_float2(v00, v01);
            float2 o1 = make_float2(v10, v11);
            *(float2*)(C + (size_t)r0 * ldc + c0) = o0;
            *(float2*)(C + (size_t)(r0 + 8) * ldc + c0) = o1;
        }
    }
}

static void launch_gemm(int epi, int M, int N, int K,
                        const float* A, int lda, const float* B, int ldb,
                        float* C, int ldc, const float* bias, const float* res,
                        cudaStream_t st)
{
    dim3 grid(N / 128, M / 128);
    switch (epi) {
        case 0: tgemm_k<0><<<grid, 256, 0, st>>>(M, N, K, A, lda, B, ldb, C, ldc, bias, res); break;
        case 1: tgemm_k<1><<<grid, 256, 0, st>>>(M, N, K, A, lda, B, ldb, C, ldc, bias, res); break;
        case 2: tgemm_k<2><<<grid, 256, 0, st>>>(M, N, K, A, lda, B, ldb, C, ldc, bias, res); break;
        default: tgemm_k<3><<<grid, 256, 0, st>>>(M, N, K, A, lda, B, ldb, C, ldc, bias, res); break;
    }
}

// ---------------- split-K GEMM for Wx: [2048 x 96] = xc[2048x2048] @ Wx ----------------
__global__ __launch_bounds__(256)
void sgemm96_splitk_k(const float* __restrict__ A, int lda, int K,
                      const float* __restrict__ B,
                      float* __restrict__ Cp)
{
    __shared__ float As[16][132];
    __shared__ float Bs[16][96];
    const int tid = threadIdx.x;
    const int split = blockIdx.x;
    const int bm = blockIdx.y * 128;
    const int kchunk = K / cWXS;
    const int kbase = split * kchunk;
    const int tx = tid & 15, ty = tid >> 4;
    const int ar0 = tid >> 2, ak0 = (tid & 3) * 4;
    const int brow = tid >> 4, bcb = (tid & 15) * 6;

    float acc[8][6];
    #pragma unroll
    for (int i = 0; i < 8; i++)
        #pragma unroll
        for (int j = 0; j < 6; j++) acc[i][j] = 0.f;

    for (int k0 = 0; k0 < kchunk; k0 += 16) {
        int kg = kbase + k0;
        float4 a0 = *(const float4*)(A + (size_t)(bm + ar0) * lda + kg + ak0);
        float4 a1 = *(const float4*)(A + (size_t)(bm + ar0 + 64) * lda + kg + ak0);
        As[ak0 + 0][ar0] = a0.x; As[ak0 + 1][ar0] = a0.y;
        As[ak0 + 2][ar0] = a0.z; As[ak0 + 3][ar0] = a0.w;
        As[ak0 + 0][ar0 + 64] = a1.x; As[ak0 + 1][ar0 + 64] = a1.y;
        As[ak0 + 2][ar0 + 64] = a1.z; As[ak0 + 3][ar0 + 64] = a1.w;
        #pragma unroll
        for (int j = 0; j < 6; j++)
            Bs[brow][bcb + j] = B[(size_t)(kg + brow) * 96 + bcb + j];
        __syncthreads();
        #pragma unroll
        for (int kk = 0; kk < 16; kk++) {
            float ra[8], rb[6];
            *(float4*)&ra[0] = *(const float4*)&As[kk][ty * 8];
            *(float4*)&ra[4] = *(const float4*)&As[kk][ty * 8 + 4];
            #pragma unroll
            for (int j = 0; j < 6; j++) rb[j] = Bs[kk][tx * 6 + j];
            #pragma unroll
            for (int i = 0; i < 8; i++)
                #pragma unroll
                for (int j = 0; j < 6; j++) acc[i][j] += ra[i] * rb[j];
        }
        __syncthreads();
    }
    float* out = Cp + (size_t)split * cBL * 96;
    #pragma unroll
    for (int i = 0; i < 8; i++) {
        int r = bm + ty * 8 + i;
        #pragma unroll
        for (int j = 0; j < 6; j++)
            out[(size_t)r * 96 + tx * 6 + j] = acc[i][j];
    }
}

__global__ void reduce96_k(const float* __restrict__ Cp, float* __restrict__ C) {
    int i = blockIdx.x * 256 + threadIdx.x;
    float s = 0.f;
    #pragma unroll
    for (int p = 0; p < cWXS; p++) s += Cp[(size_t)p * cBL * 96 + i];
    C[i] = s;
}

// ---------------- copy x -> three branch states ----------------
__global__ void copy3_k(const float* __restrict__ x, float* a, float* b, float* c) {
    int i = blockIdx.x * 256 + threadIdx.x;
    float4 v = ((const float4*)x)[i];
    ((float4*)a)[i] = v;
    ((float4*)b)[i] = v;
    ((float4*)c)[i] = v;
}

// ---------------- RMSNorm ----------------
__global__ void rmsnorm_k(const float* __restrict__ x, const float* __restrict__ w,
                          float* __restrict__ o)
{
    __shared__ float sm[8];
    int row = blockIdx.x, tid = threadIdx.x;
    float4 v = ((const float4*)(x + (size_t)row * cD))[tid];
    float ss = v.x * v.x + v.y * v.y + v.z * v.z + v.w * v.w;
    float tot = block_sum256(ss, sm);
    float sc = rsqrtf(tot * (1.f / cD) + 1e-6f);
    float4 wv = ((const float4*)w)[tid];
    float4 r;
    r.x = v.x * sc * wv.x; r.y = v.y * sc * wv.y;
    r.z = v.z * sc * wv.z; r.w = v.w * sc * wv.w;
    ((float4*)(o + (size_t)row * cD))[tid] = r;
}

// ---------------- mamba: depthwise conv + silu ----------------
__global__ void conv_silu_k(const float* __restrict__ xz, const float* __restrict__ cw,
                            const float* __restrict__ cb, float* __restrict__ xc)
{
    int idx = blockIdx.x * 256 + threadIdx.x;
    int c = idx & (cDI - 1);
    int t = (idx >> 11) & (cL - 1);
    int b = idx >> 21;
    float acc = cb[c];
    #pragma unroll
    for (int j = 0; j < 4; j++) {
        int tt = t + j - 3;
        if (tt >= 0)
            acc += xz[((size_t)(b * cL + tt)) * (2 * cDI) + c] * cw[j * cDI + c];
    }
    xc[idx] = acc * sigmoid_f(acc);
}

// ---------------- mamba selective scan: 8-step unroll + depth-2 pipeline ----------------
__global__ void mamba_scan_k(const float* __restrict__ delta, const float* __restrict__ xc,
                             const float* __restrict__ xdbl, const float* __restrict__ xz,
                             const float* __restrict__ Alog, const float* __restrict__ Dp,
                             float* __restrict__ y)
{
    int warp = (blockIdx.x * blockDim.x + threadIdx.x) >> 5;
    int lane = threadIdx.x & 31;
    int s = lane & 15;
    int half = lane >> 4;
    int g = warp * 2 + half;
    int b = g >> 11;
    int d = g & (cDI - 1);

    float A  = -__expf(Alog[d * cDS + s]);
    float Dd = Dp[d];
    float h = 0.f;

    float dl0[cU], u0[cU], Bv0[cU], Cv0[cU], z0[cU];
    float dl1[cU], u1[cU], Bv1[cU], Cv1[cU], z1[cU];

    #pragma unroll
    for (int j = 0; j < cU; j++) {
        int row = b * cL + j;
        dl0[j] = delta[(size_t)row * cDI + d];
        u0[j]  = xc[(size_t)row * cDI + d];
        Bv0[j] = xdbl[(size_t)row * cXDB + cDTR + s];
        Cv0[j] = xdbl[(size_t)row * cXDB + cDTR + cDS + s];
        z0[j]  = xz[(size_t)row * (2 * cDI) + cDI + d];
    }

    for (int t0 = 0; t0 < cL; t0 += cU) {
        const bool nxt = (t0 + cU < cL);
        if (nxt) {
            #pragma unroll
            for (int j = 0; j < cU; j++) {
                int row = b * cL + t0 + cU + j;
                dl1[j] = delta[(size_t)row * cDI + d];
                u1[j]  = xc[(size_t)row * cDI + d];
                Bv1[j] = xdbl[(size_t)row * cXDB + cDTR + s];
                Cv1[j] = xdbl[(size_t)row * cXDB + cDTR + cDS + s];
                z1[j]  = xz[(size_t)row * (2 * cDI) + cDI + d];
            }
        }
        #pragma unroll
        for (int j = 0; j < cU; j++) {
            float dA = __expf(dl0[j] * A);
            h = h * dA + dl0[j] * u0[j] * Bv0[j];
            float p = h * Cv0[j];
            p += __shfl_xor_sync(0xffffffffu, p, 8);
            p += __shfl_xor_sync(0xffffffffu, p, 4);
            p += __shfl_xor_sync(0xffffffffu, p, 2);
            p += __shfl_xor_sync(0xffffffffu, p, 1);
            if (s == 0) {
                float z = z0[j];
                y[(size_t)(b * cL + t0 + j) * cDI + d] = (p + Dd * u0[j]) * (z * sigmoid_f(z));
            }
        }
        if (nxt) {
            #pragma unroll
            for (int j = 0; j < cU; j++) {
                dl0[j] = dl1[j]; u0[j] = u1[j];
                Bv0[j] = Bv1[j]; Cv0[j] = Cv1[j]; z0[j] = z1[j];
            }
        }
    }
}

// ---------------- RWKV: rmsnorm + token-shift mixes ----------------
__global__ void rwkv_mix_k(const float* __restrict__ x, const float* __restrict__ norm,
                           const float* __restrict__ mu,
                           float* __restrict__ mr, float* __restrict__ mk, float* __restrict__ mv)
{
    __shared__ float sm[8];
    int row = blockIdx.x, tid = threadIdx.x;
    int t = row & (cL - 1);
    float4 vc = ((const float4*)(x + (size_t)row * cD))[tid];
    float4 vp = make_float4(0.f, 0.f, 0.f, 0.f);
    if (t > 0) vp = ((const float4*)(x + (size_t)(row - 1) * cD))[tid];
    float ssc = vc.x * vc.x + vc.y * vc.y + vc.z * vc.z + vc.w * vc.w;
    float ssp = vp.x * vp.x + vp.y * vp.y + vp.z * vp.z + vp.w * vp.w;
    float totc = block_sum256(ssc, sm);
    float totp = block_sum256(ssp, sm);
    float sc = rsqrtf(totc * (1.f / cD) + 1e-6f);
    float sp = rsqrtf(totp * (1.f / cD) + 1e-6f);
    float4 wv = ((const float4*)norm)[tid];
    float xn[4] = { vc.x * sc * wv.x, vc.y * sc * wv.y, vc.z * sc * wv.z, vc.w * sc * wv.w };
    float xs[4] = { vp.x * sp * wv.x, vp.y * sp * wv.y, vp.z * sp * wv.z, vp.w * sp * wv.w };
    float* outs[3] = { mr, mk, mv };
    #pragma unroll
    for (int j = 0; j < 3; j++) {
        float4 m4 = ((const float4*)(mu + j * cD))[tid];
        float mm[4] = { m4.x, m4.y, m4.z, m4.w };
        float4 r;
        r.x = xn[0] * mm[0] + xs[0] * (1.f - mm[0]);
        r.y = xn[1] * mm[1] + xs[1] * (1.f - mm[1]);
        r.z = xn[2] * mm[2] + xs[2] * (1.f - mm[2]);
        r.w = xn[3] * mm[3] + xs[3] * (1.f - mm[3]);
        ((float4*)(outs[j] + (size_t)row * cD))[tid] = r;
    }
}

// ---------------- RWKV scan: shuffle reduction + 4-deep smem ring prefetch ----------------
__global__ __launch_bounds__(512)
void rwkv_scan_k(const float* __restrict__ r, const float* __restrict__ k,
                 const float* __restrict__ v, const float* __restrict__ wlog,
                 const float* __restrict__ u, float* __restrict__ y)
{
    int b = blockIdx.x >> 4;
    int h = blockIdx.x & 15;
    int tid = threadIdx.x;
    int vv = tid >> 3;     // 0..63
    int kq = tid & 7;      // 0..7

    __shared__ float sr[4][64], sk[4][64], sv[4][64];

    float wreg[8], ureg[8], S[8];
    #pragma unroll
    for (int i = 0; i < 8; i++) {
        wreg[i] = __expf(-__expf(wlog[h * cDHR + kq * 8 + i]));
        ureg[i] = u[h * cDHR + kq * 8 + i];
        S[i] = 0.f;
    }

    #pragma unroll
    for (int t = 0; t < 3; t++) {
        size_t base = ((size_t)(b * cL + t)) * cD + h * cDHR;
        if (tid < 64)       sr[t][tid]       = r[base + tid];
        else if (tid < 128) sk[t][tid - 64]  = k[base + tid - 64];
        else if (tid < 192) sv[t][tid - 128] = v[base + tid - 128];
    }
    __syncthreads();

    for (int t = 0; t < cL; t++) {
        int cur = t & 3, nb = (t + 3) & 3;

        float pr = 0.f, pk = 0.f, pv = 0.f;
        const bool pf = (t + 3 < cL);
        if (pf) {
            size_t base = ((size_t)(b * cL + t + 3)) * cD + h * cDHR;
            if (tid < 64)       pr = r[base + tid];
            else if (tid < 128) pk = k[base + tid - 64];
            else if (tid < 192) pv = v[base + tid - 128];
        }

        float vt = sv[cur][vv];
        float4 k0 = *(const float4*)&sk[cur][kq * 8];
        float4 k1 = *(const float4*)&sk[cur][kq * 8 + 4];
        float4 r0 = *(const float4*)&sr[cur][kq * 8];
        float4 r1 = *(const float4*)&sr[cur][kq * 8 + 4];
        float kkv[8] = { k0.x, k0.y, k0.z, k0.w, k1.x, k1.y, k1.z, k1.w };
        float rrv[8] = { r0.x, r0.y, r0.z, r0.w, r1.x, r1.y, r1.z, r1.w };
        float yp = 0.f;
        #pragma unroll
        for (int i = 0; i < 8; i++) {
            float kvv = kkv[i] * vt;
            yp += rrv[i] * (S[i] + ureg[i] * kvv);
            S[i] = wreg[i] * S[i] + kvv;
        }
        yp += __shfl_xor_sync(0xffffffffu, yp, 1);
        yp += __shfl_xor_sync(0xffffffffu, yp, 2);
        yp += __shfl_xor_sync(0xffffffffu, yp, 4);
        if (kq == 0)
            y[((size_t)(b * cL + t)) * cD + h * cDHR + vv] = yp;

        __syncthreads();

        if (pf) {
            if (tid < 64)       sr[nb][tid]       = pr;
            else if (tid < 128) sk[nb][tid - 64]  = pk;
            else if (tid < 192) sv[nb][tid - 128] = pv;
        }
    }
}

// ---------------- MHA: one-pass online-softmax attention ----------------
__global__ __launch_bounds__(256)
void mha_flash_k(const float* __restrict__ q, const float* __restrict__ k,
                 const float* __restrict__ v, float* __restrict__ o)
{
    __shared__ float skm[64][32];
    __shared__ float svm[64][32];
    int b = blockIdx.z, h = blockIdx.y, qc = blockIdx.x;
    int tid = threadIdx.x;
    int t = qc * 256 + tid;
    size_t qbase = ((size_t)(b * cL + t) * cHA + h) * cDHA;

    float qr[32], oacc[32];
    #pragma unroll
    for (int d = 0; d < 32; d += 4) *(float4*)&qr[d] = *(const float4*)(q + qbase + d);
    #pragma unroll
    for (int d = 0; d < 32; d++) oacc[d] = 0.f;
    float m = -1e30f, l = 0.f;
    const float scale = 0.17677669529663687f;

    for (int t0 = 0; t0 < cL; t0 += 64) {
        int rr = tid >> 2, cc = (tid & 3) * 8;
        size_t kb = ((size_t)(b * cL + t0 + rr) * cHA + h) * cDHA + cc;
        *(float4*)&skm[rr][cc]     = *(const float4*)(k + kb);
        *(float4*)&skm[rr][cc + 4] = *(const float4*)(k + kb + 4);
        *(float4*)&svm[rr][cc]     = *(const float4*)(v + kb);
        *(float4*)&svm[rr][cc + 4] = *(const float4*)(v + kb + 4);
        __syncthreads();
        #pragma unroll 2
        for (int j = 0; j < 64; j++) {
            float s = 0.f;
            #pragma unroll
            for (int d = 0; d < 32; d += 4) {
                float4 kk4 = *(const float4*)&skm[j][d];
                s += qr[d] * kk4.x + qr[d + 1] * kk4.y + qr[d + 2] * kk4.z + qr[d + 3] * kk4.w;
            }
            s *= scale;
            float mn = fmaxf(m, s);
            float corr = __expf(m - mn);
            float p = __expf(s - mn);
            l = l * corr + p;
            m = mn;
            #pragma unroll
            for (int d = 0; d < 32; d += 4) {
                float4 vv4 = *(const float4*)&svm[j][d];
                oacc[d]     = oacc[d]     * corr + p * vv4.x;
                oacc[d + 1] = oacc[d + 1] * corr + p * vv4.y;
                oacc[d + 2] = oacc[d + 2] * corr + p * vv4.z;
                oacc[d + 3] = oacc[d + 3] * corr + p * vv4.w;
            }
        }
        __syncthreads();
    }
    float inv = 1.f / l;
    #pragma unroll
    for (int d = 0; d < 32; d += 4) {
        float4 r4 = make_float4(oacc[d] * inv, oacc[d + 1] * inv,
                                oacc[d + 2] * inv, oacc[d + 3] * inv);
        *(float4*)(o + qbase + d) = r4;
    }
}

// ---------------- final: concat -> linear(3) -> softmax ----------------
__global__ void final_k(const float* __restrict__ mx, const float* __restrict__ rx,
                        const float* __restrict__ tx, const float* __restrict__ fW,
                        const float* __restrict__ fb, float* __restrict__ out)
{
    int row = blockIdx.x, tid = threadIdx.x;
    float a0 = 0.f, a1 = 0.f, a2 = 0.f;
    const float* xs[3] = { mx, rx, tx };
    for (int p = 0; p < 3; p++) {
        const float* xp = xs[p] + (size_t)row * cD;
        const float* wp = fW + (size_t)p * cD * 3;
        for (int i = tid; i < cD; i += 128) {
            float vv = xp[i];
            a0 += vv * wp[i * 3 + 0];
            a1 += vv * wp[i * 3 + 1];
            a2 += vv * wp[i * 3 + 2];
        }
    }
    #pragma unroll
    for (int mk = 16; mk; mk >>= 1) {
        a0 += __shfl_xor_sync(0xffffffffu, a0, mk);
        a1 += __shfl_xor_sync(0xffffffffu, a1, mk);
        a2 += __shfl_xor_sync(0xffffffffu, a2, mk);
    }
    __shared__ float s0[4], s1[4], s2[4];
    int w = tid >> 5;
    if ((tid & 31) == 0) { s0[w] = a0; s1[w] = a1; s2[w] = a2; }
    __syncthreads();
    if (tid == 0) {
        float b0 = s0[0] + s0[1] + s0[2] + s0[3] + fb[0];
        float b1 = s1[0] + s1[1] + s1[2] + s1[3] + fb[1];
        float b2 = s2[0] + s2[1] + s2[2] + s2[3] + fb[2];
        float mm = fmaxf(b0, fmaxf(b1, b2));
        float e0 = __expf(b0 - mm), e1 = __expf(b1 - mm), e2 = __expf(b2 - mm);
        float inv = 1.f / (e0 + e1 + e2);
        out[row * 3 + 0] = e0 * inv;
        out[row * 3 + 1] = e1 * inv;
        out[row * 3 + 2] = e2 * inv;
    }
}

// ---------------- persistent stream/event resources ----------------
static cudaStream_t g_s1 = nullptr;
static cudaStream_t g_s2 = nullptr;
static cudaEvent_t  g_eF = nullptr;
static cudaEvent_t  g_e1 = nullptr;
static cudaEvent_t  g_e2 = nullptr;

// ---------------- host orchestration ----------------
extern "C" void kernel_launch(void* const* d_in, const int* in_sizes, int n_in,
                              void* d_out, int out_size)
{
    (void)in_sizes; (void)n_in; (void)out_size;
    const float* x       = (const float*)d_in[0];
    const float* m_norm  = (const float*)d_in[1];
    const float* m_Win   = (const float*)d_in[2];
    const float* m_convw = (const float*)d_in[3];
    const float* m_convb = (const float*)d_in[4];
    const float* m_Wx    = (const float*)d_in[5];
    const float* m_Wdt   = (const float*)d_in[6];
    const float* m_bdt   = (const float*)d_in[7];
    const float* m_Alog  = (const float*)d_in[8];
    const float* m_D     = (const float*)d_in[9];
    const float* m_Wout  = (const float*)d_in[10];
    const float* r_norm  = (const float*)d_in[11];
    const float* r_mu    = (const float*)d_in[12];
    const float* r_Wr    = (const float*)d_in[13];
    const float* r_Wk    = (const float*)d_in[14];
    const float* r_Wv    = (const float*)d_in[15];
    const float* r_Wo    = (const float*)d_in[16];
    const float* r_wlog  = (const float*)d_in[17];
    const float* r_u     = (const float*)d_in[18];
    const float* a_Wq    = (const float*)d_in[19];
    const float* a_bq    = (const float*)d_in[20];
    const float* a_Wk    = (const float*)d_in[21];
    const float* a_bk    = (const float*)d_in[22];
    const float* a_Wv    = (const float*)d_in[23];
    const float* a_bv    = (const float*)d_in[24];
    const float* a_Wo    = (const float*)d_in[25];
    const float* a_bo    = (const float*)d_in[26];
    const float* f_W     = (const float*)d_in[27];
    const float* f_b     = (const float*)d_in[28];
    float* out = (float*)d_out;

    float *p_mx, *p_rx, *p_tx, *p_xn, *p_xz, *p_xc, *p_xdbl, *p_wxp, *p_delta, *p_ym;
    float *p_ar, *p_ak, *p_av, *p_br, *p_bk, *p_bv, *p_y1;
    float *p_tq, *p_tk, *p_tv, *p_to;
    cudaGetSymbolAddress((void**)&p_mx, g_mx);
    cudaGetSymbolAddress((void**)&p_rx, g_rx);
    cudaGetSymbolAddress((void**)&p_tx, g_tx);
    cudaGetSymbolAddress((void**)&p_xn, g_xn);
    cudaGetSymbolAddress((void**)&p_xz, g_xz);
    cudaGetSymbolAddress((void**)&p_xc, g_xc);
    cudaGetSymbolAddress((void**)&p_xdbl, g_xdbl);
    cudaGetSymbolAddress((void**)&p_wxp, g_wxp);
    cudaGetSymbolAddress((void**)&p_delta, g_delta);
    cudaGetSymbolAddress((void**)&p_ym, g_ym);
    cudaGetSymbolAddress((void**)&p_ar, g_ar);
    cudaGetSymbolAddress((void**)&p_ak, g_ak);
    cudaGetSymbolAddress((void**)&p_av, g_av);
    cudaGetSymbolAddress((void**)&p_br, g_br);
    cudaGetSymbolAddress((void**)&p_bk, g_bk);
    cudaGetSymbolAddress((void**)&p_bv, g_bv);
    cudaGetSymbolAddress((void**)&p_y1, g_y1);
    cudaGetSymbolAddress((void**)&p_tq, g_tq);
    cudaGetSymbolAddress((void**)&p_tk, g_tk);
    cudaGetSymbolAddress((void**)&p_tv, g_tv);
    cudaGetSymbolAddress((void**)&p_to, g_to);

    if (g_s1 == nullptr) {
        cudaStreamCreateWithFlags(&g_s1, cudaStreamNonBlocking);
        cudaStreamCreateWithFlags(&g_s2, cudaStreamNonBlocking);
        cudaEventCreateWithFlags(&g_eF, cudaEventDisableTiming);
        cudaEventCreateWithFlags(&g_e1, cudaEventDisableTiming);
        cudaEventCreateWithFlags(&g_e2, cudaEventDisableTiming);
    }
    cudaStream_t s0 = 0, s1 = g_s1, s2 = g_s2;

    copy3_k<<<(cBL * cD) / 4 / 256, 256, 0, s0>>>(x, p_mx, p_rx, p_tx);

    // fork
    cudaEventRecord(g_eF, s0);
    cudaStreamWaitEvent(s1, g_eF, 0);
    cudaStreamWaitEvent(s2, g_eF, 0);

    // ---- Mamba chain (s0) ----
    for (int i = 0; i < cNM; i++) {
        rmsnorm_k<<<cBL, 256, 0, s0>>>(p_mx, m_norm + i * cD, p_xn);
        launch_gemm(0, cBL, 2 * cDI, cD, p_xn, cD,
                    m_Win + (size_t)i * cD * 2 * cDI, 2 * cDI, p_xz, 2 * cDI,
                    nullptr, nullptr, s0);
        conv_silu_k<<<(cBL * cDI) / 256, 256, 0, s0>>>(p_xz, m_convw + i * 4 * cDI,
                                                       m_convb + i * cDI, p_xc);
        sgemm96_splitk_k<<<dim3(cWXS, cBL / 128), 256, 0, s0>>>(
            p_xc, cDI, cDI, m_Wx + (size_t)i * cDI * cXDB, p_wxp);
        reduce96_k<<<(cBL * cXDB) / 256, 256, 0, s0>>>(p_wxp, p_xdbl);
        launch_gemm(2, cBL, cDI, cDTR, p_xdbl, cXDB,
                    m_Wdt + (size_t)i * cDTR * cDI, cDI, p_delta, cDI,
                    m_bdt + i * cDI, nullptr, s0);
        mamba_scan_k<<<(cB * cDI / 2) / 8, 256, 0, s0>>>(p_delta, p_xc, p_xdbl, p_xz,
                                                         m_Alog + (size_t)i * cDI * cDS,
                                                         m_D + i * cDI, p_ym);
        launch_gemm(3, cBL, cD, cDI, p_ym, cDI,
                    m_Wout + (size_t)i * cDI * cD, cD, p_mx, cD, nullptr, p_mx, s0);
    }

    // ---- RWKV chain (s1) ----
    for (int i = 0; i < cNR; i++) {
        rwkv_mix_k<<<cBL, 256, 0, s1>>>(p_rx, r_norm + i * cD,
                                        r_mu + (size_t)i * 3 * cD, p_ar, p_ak, p_av);
        launch_gemm(0, cBL, cD, cD, p_ar, cD, r_Wr + (size_t)i * cD * cD, cD,
                    p_br, cD, nullptr, nullptr, s1);
        launch_gemm(0, cBL, cD, cD, p_ak, cD, r_Wk + (size_t)i * cD * cD, cD,
                    p_bk, cD, nullptr, nullptr, s1);
        launch_gemm(0, cBL, cD, cD, p_av, cD, r_Wv + (size_t)i * cD * cD, cD,
                    p_bv, cD, nullptr, nullptr, s1);
        rwkv_scan_k<<<cB * cHR, 512, 0, s1>>>(p_br, p_bk, p_bv,
                                              r_wlog + (size_t)i * cHR * cDHR,
                                              r_u + (size_t)i * cHR * cDHR, p_y1);
        launch_gemm(3, cBL, cD, cD, p_y1, cD, r_Wo + (size_t)i * cD * cD, cD,
                    p_rx, cD, nullptr, p_rx, s1);
    }

    // ---- MHA chain (s2) ----
    for (int i = 0; i < cNT; i++) {
        launch_gemm(1, cBL, cD, cD, p_tx, cD, a_Wq + (size_t)i * cD * cD, cD,
                    p_tq, cD, a_bq + i * cD, nullptr, s2);
        launch_gemm(1, cBL, cD, cD, p_tx, cD, a_Wk + (size_t)i * cD * cD, cD,
                    p_tk, cD, a_bk + i * cD, nullptr, s2);
        launch_gemm(1, cBL, cD, cD, p_tx, cD, a_Wv + (size_t)i * cD * cD, cD,
                    p_tv, cD, a_bv + i * cD, nullptr, s2);
        mha_flash_k<<<dim3(4, cHA, cB), 256, 0, s2>>>(p_tq, p_tk, p_tv, p_to);
        launch_gemm(1, cBL, cD, cD, p_to, cD, a_Wo + (size_t)i * cD * cD, cD,
                    p_tx, cD, a_bo + i * cD, nullptr, s2);
    }

    // join
    cudaEventRecord(g_e1, s1);
    cudaEventRecord(g_e2, s2);
    cudaStreamWaitEvent(s0, g_e1, 0);
    cudaStreamWaitEvent(s0, g_e2, 0);

    final_k<<<cBL, 128, 0, s0>>>(p_mx, p_rx, p_tx, f_W, f_b, out);
}

// round 9
// speedup vs baseline: 1.2474x; 1.2474x over previous
#include <cuda_runtime.h>
#include <math.h>
#include <stdint.h>

// ---------------- problem constants ----------------
constexpr int cB   = 2;
constexpr int cL   = 1024;
constexpr int cD   = 1024;
constexpr int cDI  = 2048;
constexpr int cDS  = 16;
constexpr int cDTR = 64;
constexpr int cHR  = 16;
constexpr int cDHR = 64;
constexpr int cHA  = 32;
constexpr int cDHA = 32;
constexpr int cNM  = 6;
constexpr int cNR  = 4;
constexpr int cNT  = 2;
constexpr int cBL  = cB * cL;                 // 2048
constexpr int cXDB = cDTR + 2 * cDS;          // 96
constexpr int cWXS = 16;                      // split-K factor for Wx GEMM
constexpr int cU   = 8;                       // mamba scan time-unroll

// ---------------- scratch (no allocations allowed) ----------------
__device__ float g_mx[cBL * cD];
__device__ float g_rx[cBL * cD];
__device__ float g_tx[cBL * cD];
__device__ float g_xn[cBL * cD];
__device__ float g_xz[cBL * 2 * cDI];
__device__ float g_xc[cBL * cDI];
__device__ float g_xdbl[cBL * cXDB];
__device__ float g_wxp[cWXS * cBL * cXDB];
__device__ float g_delta[cBL * cDI];
__device__ float g_ym[cBL * cDI];
__device__ float g_ar[cBL * cD];
__device__ float g_ak[cBL * cD];
__device__ float g_av[cBL * cD];
__device__ float g_br[cBL * cD];
__device__ float g_bk[cBL * cD];
__device__ float g_bv[cBL * cD];
__device__ float g_y1[cBL * cD];
__device__ float g_tq[cBL * cD];
__device__ float g_tk[cBL * cD];
__device__ float g_tv[cBL * cD];
__device__ float g_to[cBL * cD];

// ---------------- helpers ----------------
__device__ __forceinline__ float sigmoid_f(float x) { return 1.f / (1.f + __expf(-x)); }

__device__ __forceinline__ float block_sum256(float v, float* sm) {
    __syncthreads();
    #pragma unroll
    for (int mk = 16; mk; mk >>= 1) v += __shfl_xor_sync(0xffffffffu, v, mk);
    int w = threadIdx.x >> 5;
    if ((threadIdx.x & 31) == 0) sm[w] = v;
    __syncthreads();
    if (threadIdx.x == 0) {
        float t = 0.f;
        #pragma unroll
        for (int i = 0; i < 8; i++) t += sm[i];
        sm[0] = t;
    }
    __syncthreads();
    return sm[0];
}

__device__ __forceinline__ void tf32_split(float v, float& hi, float& lo) {
    uint32_t h;
    asm("cvt.rna.tf32.f32 %0, %1;" : "=r"(h) : "f"(v));
    hi = __uint_as_float(h);
    float d = v - hi;
    uint32_t l;
    asm("cvt.rna.tf32.f32 %0, %1;" : "=r"(l) : "f"(d));
    lo = __uint_as_float(l);
}

__device__ __forceinline__ void mma8(float* c,
                                     uint32_t a0, uint32_t a1, uint32_t a2, uint32_t a3,
                                     uint32_t b0, uint32_t b1)
{
    asm volatile("mma.sync.aligned.m16n8k8.row.col.f32.tf32.tf32.f32 "
                 "{%0,%1,%2,%3}, {%4,%5,%6,%7}, {%8,%9}, {%0,%1,%2,%3};"
                 : "+f"(c[0]), "+f"(c[1]), "+f"(c[2]), "+f"(c[3])
                 : "r"(a0), "r"(a1), "r"(a2), "r"(a3), "r"(b0), "r"(b1));
}

// ---------------- TF32x3 tensor-core GEMM: C[M,N] = epi(A[M,K] @ B[K,N]) ----------------
// R7 scalar smem layout (verified conflict-free) + DOUBLE-BUFFERED tiles:
// one barrier per ktile; split/STS of next tile overlaps other warps' compute.
// EPI: 0 none, 1 +bias, 2 softplus(x+bias), 3 +res.
template <int EPI>
__global__ __launch_bounds__(256)
void tgemm_k(int M, int N, int K,
             const float* __restrict__ A, int lda,
             const float* __restrict__ B, int ldb,
             float* __restrict__ C, int ldc,
             const float* __restrict__ bias,
             const float* __restrict__ res)
{
    constexpr int ASR = 20;    // A smem row stride ([m][k], 16 + 4 pad)
    constexpr int BSR = 136;   // B smem row stride ([k][n], 128 + 8 pad)
    __shared__ float Ah[2][128][ASR], Al[2][128][ASR];
    __shared__ float Bh[2][16][BSR],  Bl[2][16][BSR];

    const int tid  = threadIdx.x;
    const int bm   = blockIdx.y * 128;
    const int bn   = blockIdx.x * 128;
    const int lane = tid & 31, warp = tid >> 5;
    const int wm = (warp >> 1) * 32;
    const int wn = (warp & 1) * 64;
    const int g  = lane >> 2, tg = lane & 3;

    const int ar = tid >> 2, ak = (tid & 3) * 4;
    const int br = tid >> 5, bc = (tid & 31) * 4;

    float acc[2][8][4];
    #pragma unroll
    for (int im = 0; im < 2; im++)
        #pragma unroll
        for (int jn = 0; jn < 8; jn++)
            #pragma unroll
            for (int q = 0; q < 4; q++) acc[im][jn][q] = 0.f;

    const float* Ap = A + (size_t)bm * lda;
    const float* Bp = B + bn;

    float4 Areg0, Areg1, Breg0, Breg1;

    auto gload = [&](int kt) {
        int k0 = kt * 16;
        Areg0 = *(const float4*)(Ap + (size_t)ar * lda + k0 + ak);
        Areg1 = *(const float4*)(Ap + (size_t)(ar + 64) * lda + k0 + ak);
        Breg0 = *(const float4*)(Bp + (size_t)(k0 + br) * ldb + bc);
        Breg1 = *(const float4*)(Bp + (size_t)(k0 + br + 8) * ldb + bc);
    };
    auto sstore = [&](int bf) {
        float h[4], l[4];
        const float* s;
        s = (const float*)&Areg0;
        #pragma unroll
        for (int i = 0; i < 4; i++) tf32_split(s[i], h[i], l[i]);
        *(float4*)&Ah[bf][ar][ak] = *(float4*)h;
        *(float4*)&Al[bf][ar][ak] = *(float4*)l;
        s = (const float*)&Areg1;
        #pragma unroll
        for (int i = 0; i < 4; i++) tf32_split(s[i], h[i], l[i]);
        *(float4*)&Ah[bf][ar + 64][ak] = *(float4*)h;
        *(float4*)&Al[bf][ar + 64][ak] = *(float4*)l;
        s = (const float*)&Breg0;
        #pragma unroll
        for (int i = 0; i < 4; i++) tf32_split(s[i], h[i], l[i]);
        *(float4*)&Bh[bf][br][bc] = *(float4*)h;
        *(float4*)&Bl[bf][br][bc] = *(float4*)l;
        s = (const float*)&Breg1;
        #pragma unroll
        for (int i = 0; i < 4; i++) tf32_split(s[i], h[i], l[i]);
        *(float4*)&Bh[bf][br + 8][bc] = *(float4*)h;
        *(float4*)&Bl[bf][br + 8][bc] = *(float4*)l;
    };

    gload(0);
    sstore(0);
    __syncthreads();

    const int nkt = K / 16;
    for (int kt = 0; kt < nkt; kt++) {
        const int bf = kt & 1;
        const bool has_next = (kt + 1 < nkt);
        if (has_next) gload(kt + 1);

        #pragma unroll
        for (int ks = 0; ks < 2; ks++) {
            const int kb = ks * 8;
            uint32_t ahf[2][4], alf[2][4];
            #pragma unroll
            for (int im = 0; im < 2; im++) {
                int m = wm + im * 16 + g;
                ahf[im][0] = __float_as_uint(Ah[bf][m][kb + tg]);
                ahf[im][1] = __float_as_uint(Ah[bf][m + 8][kb + tg]);
                ahf[im][2] = __float_as_uint(Ah[bf][m][kb + tg + 4]);
                ahf[im][3] = __float_as_uint(Ah[bf][m + 8][kb + tg + 4]);
                alf[im][0] = __float_as_uint(Al[bf][m][kb + tg]);
                alf[im][1] = __float_as_uint(Al[bf][m + 8][kb + tg]);
                alf[im][2] = __float_as_uint(Al[bf][m][kb + tg + 4]);
                alf[im][3] = __float_as_uint(Al[bf][m + 8][kb + tg + 4]);
            }
            #pragma unroll
            for (int jn = 0; jn < 8; jn++) {
                int n = wn + jn * 8 + g;
                uint32_t bh0 = __float_as_uint(Bh[bf][kb + tg][n]);
                uint32_t bh1 = __float_as_uint(Bh[bf][kb + tg + 4][n]);
                uint32_t bl0 = __float_as_uint(Bl[bf][kb + tg][n]);
                uint32_t bl1 = __float_as_uint(Bl[bf][kb + tg + 4][n]);
                #pragma unroll
                for (int im = 0; im < 2; im++) {
                    mma8(acc[im][jn], ahf[im][0], ahf[im][1], ahf[im][2], ahf[im][3], bl0, bl1);
                    mma8(acc[im][jn], alf[im][0], alf[im][1], alf[im][2], alf[im][3], bh0, bh1);
                    mma8(acc[im][jn], ahf[im][0], ahf[im][1], ahf[im][2], ahf[im][3], bh0, bh1);
                }
            }
        }

        if (has_next) {
            sstore(bf ^ 1);     // safe: bf^1 reads finished before prior barrier
            __syncthreads();    // publish for next iteration
        }
    }

    #pragma unroll
    for (int im = 0; im < 2; im++) {
        int r0 = bm + wm + im * 16 + g;
        #pragma unroll
        for (int jn = 0; jn < 8; jn++) {
            int c0 = bn + wn + jn * 8 + 2 * tg;
            float v00 = acc[im][jn][0], v01 = acc[im][jn][1];
            float v10 = acc[im][jn][2], v11 = acc[im][jn][3];
            if (EPI == 1 || EPI == 2) {
                float b0 = bias[c0], b1 = bias[c0 + 1];
                v00 += b0; v01 += b1; v10 += b0; v11 += b1;
            }
            if (EPI == 2) {
                v00 = (v00 > 15.f) ? v00 : log1pf(__expf(v00));
                v01 = (v01 > 15.f) ? v01 : log1pf(__expf(v01));
                v10 = (v10 > 15.f) ? v10 : log1pf(__expf(v10));
                v11 = (v11 > 15.f) ? v11 : log1pf(__expf(v11));
            }
            if (EPI == 3) {
                float2 rA = *(const float2*)(res + (size_t)r0 * ldc + c0);
                float2 rB = *(const float2*)(res + (size_t)(r0 + 8) * ldc + c0);
                v00 += rA.x; v01 += rA.y; v10 += rB.x; v11 += rB.y;
            }
            float2 o0 = make_float2(v00, v01);
            float2 o1 = make_float2(v10, v11);
            *(float2*)(C + (size_t)r0 * ldc + c0) = o0;
            *(float2*)(C + (size_t)(r0 + 8) * ldc + c0) = o1;
        }
    }
}

static void launch_gemm(int epi, int M, int N, int K,
                        const float* A, int lda, const float* B, int ldb,
                        float* C, int ldc, const float* bias, const float* res,
                        cudaStream_t st)
{
    dim3 grid(N / 128, M / 128);
    switch (epi) {
        case 0: tgemm_k<0><<<grid, 256, 0, st>>>(M, N, K, A, lda, B, ldb, C, ldc, bias, res); break;
        case 1: tgemm_k<1><<<grid, 256, 0, st>>>(M, N, K, A, lda, B, ldb, C, ldc, bias, res); break;
        case 2: tgemm_k<2><<<grid, 256, 0, st>>>(M, N, K, A, lda, B, ldb, C, ldc, bias, res); break;
        default: tgemm_k<3><<<grid, 256, 0, st>>>(M, N, K, A, lda, B, ldb, C, ldc, bias, res); break;
    }
}

// ---------------- split-K GEMM for Wx: [2048 x 96] = xc[2048x2048] @ Wx ----------------
__global__ __launch_bounds__(256)
void sgemm96_splitk_k(const float* __restrict__ A, int lda, int K,
                      const float* __restrict__ B,
                      float* __restrict__ Cp)
{
    __shared__ float As[16][132];
    __shared__ float Bs[16][96];
    const int tid = threadIdx.x;
    const int split = blockIdx.x;
    const int bm = blockIdx.y * 128;
    const int kchunk = K / cWXS;
    const int kbase = split * kchunk;
    const int tx = tid & 15, ty = tid >> 4;
    const int ar0 = tid >> 2, ak0 = (tid & 3) * 4;
    const int brow = tid >> 4, bcb = (tid & 15) * 6;

    float acc[8][6];
    #pragma unroll
    for (int i = 0; i < 8; i++)
        #pragma unroll
        for (int j = 0; j < 6; j++) acc[i][j] = 0.f;

    for (int k0 = 0; k0 < kchunk; k0 += 16) {
        int kg = kbase + k0;
        float4 a0 = *(const float4*)(A + (size_t)(bm + ar0) * lda + kg + ak0);
        float4 a1 = *(const float4*)(A + (size_t)(bm + ar0 + 64) * lda + kg + ak0);
        As[ak0 + 0][ar0] = a0.x; As[ak0 + 1][ar0] = a0.y;
        As[ak0 + 2][ar0] = a0.z; As[ak0 + 3][ar0] = a0.w;
        As[ak0 + 0][ar0 + 64] = a1.x; As[ak0 + 1][ar0 + 64] = a1.y;
        As[ak0 + 2][ar0 + 64] = a1.z; As[ak0 + 3][ar0 + 64] = a1.w;
        #pragma unroll
        for (int j = 0; j < 6; j++)
            Bs[brow][bcb + j] = B[(size_t)(kg + brow) * 96 + bcb + j];
        __syncthreads();
        #pragma unroll
        for (int kk = 0; kk < 16; kk++) {
            float ra[8], rb[6];
            *(float4*)&ra[0] = *(const float4*)&As[kk][ty * 8];
            *(float4*)&ra[4] = *(const float4*)&As[kk][ty * 8 + 4];
            #pragma unroll
            for (int j = 0; j < 6; j++) rb[j] = Bs[kk][tx * 6 + j];
            #pragma unroll
            for (int i = 0; i < 8; i++)
                #pragma unroll
                for (int j = 0; j < 6; j++) acc[i][j] += ra[i] * rb[j];
        }
        __syncthreads();
    }
    float* out = Cp + (size_t)split * cBL * 96;
    #pragma unroll
    for (int i = 0; i < 8; i++) {
        int r = bm + ty * 8 + i;
        #pragma unroll
        for (int j = 0; j < 6; j++)
            out[(size_t)r * 96 + tx * 6 + j] = acc[i][j];
    }
}

__global__ void reduce96_k(const float* __restrict__ Cp, float* __restrict__ C) {
    int i = blockIdx.x * 256 + threadIdx.x;
    float s = 0.f;
    #pragma unroll
    for (int p = 0; p < cWXS; p++) s += Cp[(size_t)p * cBL * 96 + i];
    C[i] = s;
}

// ---------------- copy x -> three branch states ----------------
__global__ void copy3_k(const float* __restrict__ x, float* a, float* b, float* c) {
    int i = blockIdx.x * 256 + threadIdx.x;
    float4 v = ((const float4*)x)[i];
    ((float4*)a)[i] = v;
    ((float4*)b)[i] = v;
    ((float4*)c)[i] = v;
}

// ---------------- RMSNorm ----------------
__global__ void rmsnorm_k(const float* __restrict__ x, const float* __restrict__ w,
                          float* __restrict__ o)
{
    __shared__ float sm[8];
    int row = blockIdx.x, tid = threadIdx.x;
    float4 v = ((const float4*)(x + (size_t)row * cD))[tid];
    float ss = v.x * v.x + v.y * v.y + v.z * v.z + v.w * v.w;
    float tot = block_sum256(ss, sm);
    float sc = rsqrtf(tot * (1.f / cD) + 1e-6f);
    float4 wv = ((const float4*)w)[tid];
    float4 r;
    r.x = v.x * sc * wv.x; r.y = v.y * sc * wv.y;
    r.z = v.z * sc * wv.z; r.w = v.w * sc * wv.w;
    ((float4*)(o + (size_t)row * cD))[tid] = r;
}

// ---------------- mamba: depthwise conv + silu ----------------
__global__ void conv_silu_k(const float* __restrict__ xz, const float* __restrict__ cw,
                            const float* __restrict__ cb, float* __restrict__ xc)
{
    int idx = blockIdx.x * 256 + threadIdx.x;
    int c = idx & (cDI - 1);
    int t = (idx >> 11) & (cL - 1);
    int b = idx >> 21;
    float acc = cb[c];
    #pragma unroll
    for (int j = 0; j < 4; j++) {
        int tt = t + j - 3;
        if (tt >= 0)
            acc += xz[((size_t)(b * cL + tt)) * (2 * cDI) + c] * cw[j * cDI + c];
    }
    xc[idx] = acc * sigmoid_f(acc);
}

// ---------------- mamba selective scan: 8-step unroll + depth-2 pipeline ----------------
__global__ void mamba_scan_k(const float* __restrict__ delta, const float* __restrict__ xc,
                             const float* __restrict__ xdbl, const float* __restrict__ xz,
                             const float* __restrict__ Alog, const float* __restrict__ Dp,
                             float* __restrict__ y)
{
    int warp = (blockIdx.x * blockDim.x + threadIdx.x) >> 5;
    int lane = threadIdx.x & 31;
    int s = lane & 15;
    int half = lane >> 4;
    int g = warp * 2 + half;
    int b = g >> 11;
    int d = g & (cDI - 1);

    float A  = -__expf(Alog[d * cDS + s]);
    float Dd = Dp[d];
    float h = 0.f;

    float dl0[cU], u0[cU], Bv0[cU], Cv0[cU], z0[cU];
    float dl1[cU], u1[cU], Bv1[cU], Cv1[cU], z1[cU];

    #pragma unroll
    for (int j = 0; j < cU; j++) {
        int row = b * cL + j;
        dl0[j] = delta[(size_t)row * cDI + d];
        u0[j]  = xc[(size_t)row * cDI + d];
        Bv0[j] = xdbl[(size_t)row * cXDB + cDTR + s];
        Cv0[j] = xdbl[(size_t)row * cXDB + cDTR + cDS + s];
        z0[j]  = xz[(size_t)row * (2 * cDI) + cDI + d];
    }

    for (int t0 = 0; t0 < cL; t0 += cU) {
        const bool nxt = (t0 + cU < cL);
        if (nxt) {
            #pragma unroll
            for (int j = 0; j < cU; j++) {
                int row = b * cL + t0 + cU + j;
                dl1[j] = delta[(size_t)row * cDI + d];
                u1[j]  = xc[(size_t)row * cDI + d];
                Bv1[j] = xdbl[(size_t)row * cXDB + cDTR + s];
                Cv1[j] = xdbl[(size_t)row * cXDB + cDTR + cDS + s];
                z1[j]  = xz[(size_t)row * (2 * cDI) + cDI + d];
            }
        }
        #pragma unroll
        for (int j = 0; j < cU; j++) {
            float dA = __expf(dl0[j] * A);
            h = h * dA + dl0[j] * u0[j] * Bv0[j];
            float p = h * Cv0[j];
            p += __shfl_xor_sync(0xffffffffu, p, 8);
            p += __shfl_xor_sync(0xffffffffu, p, 4);
            p += __shfl_xor_sync(0xffffffffu, p, 2);
            p += __shfl_xor_sync(0xffffffffu, p, 1);
            if (s == 0) {
                float z = z0[j];
                y[(size_t)(b * cL + t0 + j) * cDI + d] = (p + Dd * u0[j]) * (z * sigmoid_f(z));
            }
        }
        if (nxt) {
            #pragma unroll
            for (int j = 0; j < cU; j++) {
                dl0[j] = dl1[j]; u0[j] = u1[j];
                Bv0[j] = Bv1[j]; Cv0[j] = Cv1[j]; z0[j] = z1[j];
            }
        }
    }
}

// ---------------- RWKV: rmsnorm + token-shift mixes ----------------
__global__ void rwkv_mix_k(const float* __restrict__ x, const float* __restrict__ norm,
                           const float* __restrict__ mu,
                           float* __restrict__ mr, float* __restrict__ mk, float* __restrict__ mv)
{
    __shared__ float sm[8];
    int row = blockIdx.x, tid = threadIdx.x;
    int t = row & (cL - 1);
    float4 vc = ((const float4*)(x + (size_t)row * cD))[tid];
    float4 vp = make_float4(0.f, 0.f, 0.f, 0.f);
    if (t > 0) vp = ((const float4*)(x + (size_t)(row - 1) * cD))[tid];
    float ssc = vc.x * vc.x + vc.y * vc.y + vc.z * vc.z + vc.w * vc.w;
    float ssp = vp.x * vp.x + vp.y * vp.y + vp.z * vp.z + vp.w * vp.w;
    float totc = block_sum256(ssc, sm);
    float totp = block_sum256(ssp, sm);
    float sc = rsqrtf(totc * (1.f / cD) + 1e-6f);
    float sp = rsqrtf(totp * (1.f / cD) + 1e-6f);
    float4 wv = ((const float4*)norm)[tid];
    float xn[4] = { vc.x * sc * wv.x, vc.y * sc * wv.y, vc.z * sc * wv.z, vc.w * sc * wv.w };
    float xs[4] = { vp.x * sp * wv.x, vp.y * sp * wv.y, vp.z * sp * wv.z, vp.w * sp * wv.w };
    float* outs[3] = { mr, mk, mv };
    #pragma unroll
    for (int j = 0; j < 3; j++) {
        float4 m4 = ((const float4*)(mu + j * cD))[tid];
        float mm[4] = { m4.x, m4.y, m4.z, m4.w };
        float4 r;
        r.x = xn[0] * mm[0] + xs[0] * (1.f - mm[0]);
        r.y = xn[1] * mm[1] + xs[1] * (1.f - mm[1]);
        r.z = xn[2] * mm[2] + xs[2] * (1.f - mm[2]);
        r.w = xn[3] * mm[3] + xs[3] * (1.f - mm[3]);
        ((float4*)(outs[j] + (size_t)row * cD))[tid] = r;
    }
}

// ---------------- RWKV scan: shuffle reduction + 4-deep smem ring prefetch ----------------
__global__ __launch_bounds__(512)
void rwkv_scan_k(const float* __restrict__ r, const float* __restrict__ k,
                 const float* __restrict__ v, const float* __restrict__ wlog,
                 const float* __restrict__ u, float* __restrict__ y)
{
    int b = blockIdx.x >> 4;
    int h = blockIdx.x & 15;
    int tid = threadIdx.x;
    int vv = tid >> 3;     // 0..63
    int kq = tid & 7;      // 0..7

    __shared__ float sr[4][64], sk[4][64], sv[4][64];

    float wreg[8], ureg[8], S[8];
    #pragma unroll
    for (int i = 0; i < 8; i++) {
        wreg[i] = __expf(-__expf(wlog[h * cDHR + kq * 8 + i]));
        ureg[i] = u[h * cDHR + kq * 8 + i];
        S[i] = 0.f;
    }

    #pragma unroll
    for (int t = 0; t < 3; t++) {
        size_t base = ((size_t)(b * cL + t)) * cD + h * cDHR;
        if (tid < 64)       sr[t][tid]       = r[base + tid];
        else if (tid < 128) sk[t][tid - 64]  = k[base + tid - 64];
        else if (tid < 192) sv[t][tid - 128] = v[base + tid - 128];
    }
    __syncthreads();

    for (int t = 0; t < cL; t++) {
        int cur = t & 3, nb = (t + 3) & 3;

        float pr = 0.f, pk = 0.f, pv = 0.f;
        const bool pf = (t + 3 < cL);
        if (pf) {
            size_t base = ((size_t)(b * cL + t + 3)) * cD + h * cDHR;
            if (tid < 64)       pr = r[base + tid];
            else if (tid < 128) pk = k[base + tid - 64];
            else if (tid < 192) pv = v[base + tid - 128];
        }

        float vt = sv[cur][vv];
        float4 k0 = *(const float4*)&sk[cur][kq * 8];
        float4 k1 = *(const float4*)&sk[cur][kq * 8 + 4];
        float4 r0 = *(const float4*)&sr[cur][kq * 8];
        float4 r1 = *(const float4*)&sr[cur][kq * 8 + 4];
        float kkv[8] = { k0.x, k0.y, k0.z, k0.w, k1.x, k1.y, k1.z, k1.w };
        float rrv[8] = { r0.x, r0.y, r0.z, r0.w, r1.x, r1.y, r1.z, r1.w };
        float yp = 0.f;
        #pragma unroll
        for (int i = 0; i < 8; i++) {
            float kvv = kkv[i] * vt;
            yp += rrv[i] * (S[i] + ureg[i] * kvv);
            S[i] = wreg[i] * S[i] + kvv;
        }
        yp += __shfl_xor_sync(0xffffffffu, yp, 1);
        yp += __shfl_xor_sync(0xffffffffu, yp, 2);
        yp += __shfl_xor_sync(0xffffffffu, yp, 4);
        if (kq == 0)
            y[((size_t)(b * cL + t)) * cD + h * cDHR + vv] = yp;

        __syncthreads();

        if (pf) {
            if (tid < 64)       sr[nb][tid]       = pr;
            else if (tid < 128) sk[nb][tid - 64]  = pk;
            else if (tid < 192) sv[nb][tid - 128] = pv;
        }
    }
}

// ---------------- MHA: one-pass online-softmax attention ----------------
__global__ __launch_bounds__(256)
void mha_flash_k(const float* __restrict__ q, const float* __restrict__ k,
                 const float* __restrict__ v, float* __restrict__ o)
{
    __shared__ float skm[64][32];
    __shared__ float svm[64][32];
    int b = blockIdx.z, h = blockIdx.y, qc = blockIdx.x;
    int tid = threadIdx.x;
    int t = qc * 256 + tid;
    size_t qbase = ((size_t)(b * cL + t) * cHA + h) * cDHA;

    float qr[32], oacc[32];
    #pragma unroll
    for (int d = 0; d < 32; d += 4) *(float4*)&qr[d] = *(const float4*)(q + qbase + d);
    #pragma unroll
    for (int d = 0; d < 32; d++) oacc[d] = 0.f;
    float m = -1e30f, l = 0.f;
    const float scale = 0.17677669529663687f;

    for (int t0 = 0; t0 < cL; t0 += 64) {
        int rr = tid >> 2, cc = (tid & 3) * 8;
        size_t kb = ((size_t)(b * cL + t0 + rr) * cHA + h) * cDHA + cc;
        *(float4*)&skm[rr][cc]     = *(const float4*)(k + kb);
        *(float4*)&skm[rr][cc + 4] = *(const float4*)(k + kb + 4);
        *(float4*)&svm[rr][cc]     = *(const float4*)(v + kb);
        *(float4*)&svm[rr][cc + 4] = *(const float4*)(v + kb + 4);
        __syncthreads();
        #pragma unroll 2
        for (int j = 0; j < 64; j++) {
            float s = 0.f;
            #pragma unroll
            for (int d = 0; d < 32; d += 4) {
                float4 kk4 = *(const float4*)&skm[j][d];
                s += qr[d] * kk4.x + qr[d + 1] * kk4.y + qr[d + 2] * kk4.z + qr[d + 3] * kk4.w;
            }
            s *= scale;
            float mn = fmaxf(m, s);
            float corr = __expf(m - mn);
            float p = __expf(s - mn);
            l = l * corr + p;
            m = mn;
            #pragma unroll
            for (int d = 0; d < 32; d += 4) {
                float4 vv4 = *(const float4*)&svm[j][d];
                oacc[d]     = oacc[d]     * corr + p * vv4.x;
                oacc[d + 1] = oacc[d + 1] * corr + p * vv4.y;
                oacc[d + 2] = oacc[d + 2] * corr + p * vv4.z;
                oacc[d + 3] = oacc[d + 3] * corr + p * vv4.w;
            }
        }
        __syncthreads();
    }
    float inv = 1.f / l;
    #pragma unroll
    for (int d = 0; d < 32; d += 4) {
        float4 r4 = make_float4(oacc[d] * inv, oacc[d + 1] * inv,
                                oacc[d + 2] * inv, oacc[d + 3] * inv);
        *(float4*)(o + qbase + d) = r4;
    }
}

// ---------------- final: concat -> linear(3) -> softmax ----------------
__global__ void final_k(const float* __restrict__ mx, const float* __restrict__ rx,
                        const float* __restrict__ tx, const float* __restrict__ fW,
                        const float* __restrict__ fb, float* __restrict__ out)
{
    int row = blockIdx.x, tid = threadIdx.x;
    float a0 = 0.f, a1 = 0.f, a2 = 0.f;
    const float* xs[3] = { mx, rx, tx };
    for (int p = 0; p < 3; p++) {
        const float* xp = xs[p] + (size_t)row * cD;
        const float* wp = fW + (size_t)p * cD * 3;
        for (int i = tid; i < cD; i += 128) {
            float vv = xp[i];
            a0 += vv * wp[i * 3 + 0];
            a1 += vv * wp[i * 3 + 1];
            a2 += vv * wp[i * 3 + 2];
        }
    }
    #pragma unroll
    for (int mk = 16; mk; mk >>= 1) {
        a0 += __shfl_xor_sync(0xffffffffu, a0, mk);
        a1 += __shfl_xor_sync(0xffffffffu, a1, mk);
        a2 += __shfl_xor_sync(0xffffffffu, a2, mk);
    }
    __shared__ float s0[4], s1[4], s2[4];
    int w = tid >> 5;
    if ((tid & 31) == 0) { s0[w] = a0; s1[w] = a1; s2[w] = a2; }
    __syncthreads();
    if (tid == 0) {
        float b0 = s0[0] + s0[1] + s0[2] + s0[3] + fb[0];
        float b1 = s1[0] + s1[1] + s1[2] + s1[3] + fb[1];
        float b2 = s2[0] + s2[1] + s2[2] + s2[3] + fb[2];
        float mm = fmaxf(b0, fmaxf(b1, b2));
        float e0 = __expf(b0 - mm), e1 = __expf(b1 - mm), e2 = __expf(b2 - mm);
        float inv = 1.f / (e0 + e1 + e2);
        out[row * 3 + 0] = e0 * inv;
        out[row * 3 + 1] = e1 * inv;
        out[row * 3 + 2] = e2 * inv;
    }
}

// ---------------- persistent stream/event resources ----------------
static cudaStream_t g_s1 = nullptr;
static cudaStream_t g_s2 = nullptr;
static cudaEvent_t  g_eF = nullptr;
static cudaEvent_t  g_e1 = nullptr;
static cudaEvent_t  g_e2 = nullptr;

// ---------------- host orchestration ----------------
extern "C" void kernel_launch(void* const* d_in, const int* in_sizes, int n_in,
                              void* d_out, int out_size)
{
    (void)in_sizes; (void)n_in; (void)out_size;
    const float* x       = (const float*)d_in[0];
    const float* m_norm  = (const float*)d_in[1];
    const float* m_Win   = (const float*)d_in[2];
    const float* m_convw = (const float*)d_in[3];
    const float* m_convb = (const float*)d_in[4];
    const float* m_Wx    = (const float*)d_in[5];
    const float* m_Wdt   = (const float*)d_in[6];
    const float* m_bdt   = (const float*)d_in[7];
    const float* m_Alog  = (const float*)d_in[8];
    const float* m_D     = (const float*)d_in[9];
    const float* m_Wout  = (const float*)d_in[10];
    const float* r_norm  = (const float*)d_in[11];
    const float* r_mu    = (const float*)d_in[12];
    const float* r_Wr    = (const float*)d_in[13];
    const float* r_Wk    = (const float*)d_in[14];
    const float* r_Wv    = (const float*)d_in[15];
    const float* r_Wo    = (const float*)d_in[16];
    const float* r_wlog  = (const float*)d_in[17];
    const float* r_u     = (const float*)d_in[18];
    const float* a_Wq    = (const float*)d_in[19];
    const float* a_bq    = (const float*)d_in[20];
    const float* a_Wk    = (const float*)d_in[21];
    const float* a_bk    = (const float*)d_in[22];
    const float* a_Wv    = (const float*)d_in[23];
    const float* a_bv    = (const float*)d_in[24];
    const float* a_Wo    = (const float*)d_in[25];
    const float* a_bo    = (const float*)d_in[26];
    const float* f_W     = (const float*)d_in[27];
    const float* f_b     = (const float*)d_in[28];
    float* out = (float*)d_out;

    float *p_mx, *p_rx, *p_tx, *p_xn, *p_xz, *p_xc, *p_xdbl, *p_wxp, *p_delta, *p_ym;
    float *p_ar, *p_ak, *p_av, *p_br, *p_bk, *p_bv, *p_y1;
    float *p_tq, *p_tk, *p_tv, *p_to;
    cudaGetSymbolAddress((void**)&p_mx, g_mx);
    cudaGetSymbolAddress((void**)&p_rx, g_rx);
    cudaGetSymbolAddress((void**)&p_tx, g_tx);
    cudaGetSymbolAddress((void**)&p_xn, g_xn);
    cudaGetSymbolAddress((void**)&p_xz, g_xz);
    cudaGetSymbolAddress((void**)&p_xc, g_xc);
    cudaGetSymbolAddress((void**)&p_xdbl, g_xdbl);
    cudaGetSymbolAddress((void**)&p_wxp, g_wxp);
    cudaGetSymbolAddress((void**)&p_delta, g_delta);
    cudaGetSymbolAddress((void**)&p_ym, g_ym);
    cudaGetSymbolAddress((void**)&p_ar, g_ar);
    cudaGetSymbolAddress((void**)&p_ak, g_ak);
    cudaGetSymbolAddress((void**)&p_av, g_av);
    cudaGetSymbolAddress((void**)&p_br, g_br);
    cudaGetSymbolAddress((void**)&p_bk, g_bk);
    cudaGetSymbolAddress((void**)&p_bv, g_bv);
    cudaGetSymbolAddress((void**)&p_y1, g_y1);
    cudaGetSymbolAddress((void**)&p_tq, g_tq);
    cudaGetSymbolAddress((void**)&p_tk, g_tk);
    cudaGetSymbolAddress((void**)&p_tv, g_tv);
    cudaGetSymbolAddress((void**)&p_to, g_to);

    if (g_s1 == nullptr) {
        cudaStreamCreateWithFlags(&g_s1, cudaStreamNonBlocking);
        cudaStreamCreateWithFlags(&g_s2, cudaStreamNonBlocking);
        cudaEventCreateWithFlags(&g_eF, cudaEventDisableTiming);
        cudaEventCreateWithFlags(&g_e1, cudaEventDisableTiming);
        cudaEventCreateWithFlags(&g_e2, cudaEventDisableTiming);
    }
    cudaStream_t s0 = 0, s1 = g_s1, s2 = g_s2;

    copy3_k<<<(cBL * cD) / 4 / 256, 256, 0, s0>>>(x, p_mx, p_rx, p_tx);

    // fork
    cudaEventRecord(g_eF, s0);
    cudaStreamWaitEvent(s1, g_eF, 0);
    cudaStreamWaitEvent(s2, g_eF, 0);

    // ---- Mamba chain (s0) ----
    for (int i = 0; i < cNM; i++) {
        rmsnorm_k<<<cBL, 256, 0, s0>>>(p_mx, m_norm + i * cD, p_xn);
        launch_gemm(0, cBL, 2 * cDI, cD, p_xn, cD,
                    m_Win + (size_t)i * cD * 2 * cDI, 2 * cDI, p_xz, 2 * cDI,
                    nullptr, nullptr, s0);
        conv_silu_k<<<(cBL * cDI) / 256, 256, 0, s0>>>(p_xz, m_convw + i * 4 * cDI,
                                                       m_convb + i * cDI, p_xc);
        sgemm96_splitk_k<<<dim3(cWXS, cBL / 128), 256, 0, s0>>>(
            p_xc, cDI, cDI, m_Wx + (size_t)i * cDI * cXDB, p_wxp);
        reduce96_k<<<(cBL * cXDB) / 256, 256, 0, s0>>>(p_wxp, p_xdbl);
        launch_gemm(2, cBL, cDI, cDTR, p_xdbl, cXDB,
                    m_Wdt + (size_t)i * cDTR * cDI, cDI, p_delta, cDI,
                    m_bdt + i * cDI, nullptr, s0);
        mamba_scan_k<<<(cB * cDI / 2) / 8, 256, 0, s0>>>(p_delta, p_xc, p_xdbl, p_xz,
                                                         m_Alog + (size_t)i * cDI * cDS,
                                                         m_D + i * cDI, p_ym);
        launch_gemm(3, cBL, cD, cDI, p_ym, cDI,
                    m_Wout + (size_t)i * cDI * cD, cD, p_mx, cD, nullptr, p_mx, s0);
    }

    // ---- RWKV chain (s1) ----
    for (int i = 0; i < cNR; i++) {
        rwkv_mix_k<<<cBL, 256, 0, s1>>>(p_rx, r_norm + i * cD,
                                        r_mu + (size_t)i * 3 * cD, p_ar, p_ak, p_av);
        launch_gemm(0, cBL, cD, cD, p_ar, cD, r_Wr + (size_t)i * cD * cD, cD,
                    p_br, cD, nullptr, nullptr, s1);
        launch_gemm(0, cBL, cD, cD, p_ak, cD, r_Wk + (size_t)i * cD * cD, cD,
                    p_bk, cD, nullptr, nullptr, s1);
        launch_gemm(0, cBL, cD, cD, p_av, cD, r_Wv + (size_t)i * cD * cD, cD,
                    p_bv, cD, nullptr, nullptr, s1);
        rwkv_scan_k<<<cB * cHR, 512, 0, s1>>>(p_br, p_bk, p_bv,
                                              r_wlog + (size_t)i * cHR * cDHR,
                                              r_u + (size_t)i * cHR * cDHR, p_y1);
        launch_gemm(3, cBL, cD, cD, p_y1, cD, r_Wo + (size_t)i * cD * cD, cD,
                    p_rx, cD, nullptr, p_rx, s1);
    }

    // ---- MHA chain (s2) ----
    for (int i = 0; i < cNT; i++) {
        launch_gemm(1, cBL, cD, cD, p_tx, cD, a_Wq + (size_t)i * cD * cD, cD,
                    p_tq, cD, a_bq + i * cD, nullptr, s2);
        launch_gemm(1, cBL, cD, cD, p_tx, cD, a_Wk + (size_t)i * cD * cD, cD,
                    p_tk, cD, a_bk + i * cD, nullptr, s2);
        launch_gemm(1, cBL, cD, cD, p_tx, cD, a_Wv + (size_t)i * cD * cD, cD,
                    p_tv, cD, a_bv + i * cD, nullptr, s2);
        mha_flash_k<<<dim3(4, cHA, cB), 256, 0, s2>>>(p_tq, p_tk, p_tv, p_to);
        launch_gemm(1, cBL, cD, cD, p_to, cD, a_Wo + (size_t)i * cD * cD, cD,
                    p_tx, cD, a_bo + i * cD, nullptr, s2);
    }

    // join
    cudaEventRecord(g_e1, s1);
    cudaEventRecord(g_e2, s2);
    cudaStreamWaitEvent(s0, g_e1, 0);
    cudaStreamWaitEvent(s0, g_e2, 0);

    final_k<<<cBL, 128, 0, s0>>>(p_mx, p_rx, p_tx, f_W, f_b, out);
}

// round 10
// speedup vs baseline: 1.5934x; 1.2774x over previous
#include <cuda_runtime.h>
#include <cuda_bf16.h>
#include <math.h>
#include <stdint.h>

// ---------------- problem constants ----------------
constexpr int cB   = 2;
constexpr int cL   = 1024;
constexpr int cD   = 1024;
constexpr int cDI  = 2048;
constexpr int cDS  = 16;
constexpr int cDTR = 64;
constexpr int cHR  = 16;
constexpr int cDHR = 64;
constexpr int cHA  = 32;
constexpr int cDHA = 32;
constexpr int cNM  = 6;
constexpr int cNR  = 4;
constexpr int cNT  = 2;
constexpr int cBL  = cB * cL;                 // 2048
constexpr int cXDB = cDTR + 2 * cDS;          // 96
constexpr int cWXS = 16;                      // split-K factor for Wx GEMM
constexpr int cU   = 8;                       // mamba scan time-unroll

// ---------------- scratch (no allocations allowed) ----------------
__device__ float g_mx[cBL * cD];
__device__ float g_rx[cBL * cD];
__device__ float g_tx[cBL * cD];
__device__ float g_xn[cBL * cD];
__device__ float g_xz[cBL * 2 * cDI];
__device__ float g_xc[cBL * cDI];
__device__ float g_xdbl[cBL * cXDB];
__device__ float g_wxp[cWXS * cBL * cXDB];
__device__ float g_delta[cBL * cDI];
__device__ float g_ym[cBL * cDI];
__device__ float g_ar[cBL * cD];
__device__ float g_ak[cBL * cD];
__device__ float g_av[cBL * cD];
__device__ float g_br[cBL * cD];
__device__ float g_bk[cBL * cD];
__device__ float g_bv[cBL * cD];
__device__ float g_y1[cBL * cD];
__device__ float g_tq[cBL * cD];
__device__ float g_tk[cBL * cD];
__device__ float g_tv[cBL * cD];
__device__ float g_to[cBL * cD];

// ---------------- helpers ----------------
__device__ __forceinline__ float sigmoid_f(float x) { return 1.f / (1.f + __expf(-x)); }

__device__ __forceinline__ float block_sum256(float v, float* sm) {
    __syncthreads();
    #pragma unroll
    for (int mk = 16; mk; mk >>= 1) v += __shfl_xor_sync(0xffffffffu, v, mk);
    int w = threadIdx.x >> 5;
    if ((threadIdx.x & 31) == 0) sm[w] = v;
    __syncthreads();
    if (threadIdx.x == 0) {
        float t = 0.f;
        #pragma unroll
        for (int i = 0; i < 8; i++) t += sm[i];
        sm[0] = t;
    }
    __syncthreads();
    return sm[0];
}

// split (a, b) into bf16 hi and lo packed pairs (low half = a = lower k index)
__device__ __forceinline__ void bf_split_pack(float a, float b, uint32_t& hp, uint32_t& lp) {
    __nv_bfloat16 ha = __float2bfloat16_rn(a);
    __nv_bfloat16 hb = __float2bfloat16_rn(b);
    __nv_bfloat16 la = __float2bfloat16_rn(a - __bfloat162float(ha));
    __nv_bfloat16 lb = __float2bfloat16_rn(b - __bfloat162float(hb));
    __nv_bfloat162 hv = __halves2bfloat162(ha, hb);
    __nv_bfloat162 lv = __halves2bfloat162(la, lb);
    hp = *reinterpret_cast<uint32_t*>(&hv);
    lp = *reinterpret_cast<uint32_t*>(&lv);
}

__device__ __forceinline__ void mma16(float* c,
                                      uint32_t a0, uint32_t a1, uint32_t a2, uint32_t a3,
                                      uint32_t b0, uint32_t b1)
{
    asm volatile("mma.sync.aligned.m16n8k16.row.col.f32.bf16.bf16.f32 "
                 "{%0,%1,%2,%3}, {%4,%5,%6,%7}, {%8,%9}, {%0,%1,%2,%3};"
                 : "+f"(c[0]), "+f"(c[1]), "+f"(c[2]), "+f"(c[3])
                 : "r"(a0), "r"(a1), "r"(a2), "r"(a3), "r"(b0), "r"(b1));
}

// ---------------- BF16x3 tensor-core GEMM: C[M,N] = epi(A[M,K] @ B[K,N]) ----------------
// fp32 operands split to bf16 hi/lo; D = Ah*Bl + Al*Bh + Ah*Bh (error ~2^-16).
// m16n8k16: one k-step per 16-wide ktile -> half the HMMA count of tf32 m16n8k8.
// smem pre-packed bf16x2 along k: A [m][kp] stride 12 u32, B [kp][n] stride 136 u32
// (both verified conflict-free). Double buffered, one barrier per ktile.
// EPI: 0 none, 1 +bias, 2 softplus(x+bias), 3 +res.
template <int EPI>
__global__ __launch_bounds__(256)
void tgemm_k(int M, int N, int K,
             const float* __restrict__ A, int lda,
             const float* __restrict__ B, int ldb,
             float* __restrict__ C, int ldc,
             const float* __restrict__ bias,
             const float* __restrict__ res)
{
    constexpr int ASR = 12;    // A packed row stride in u32 (8 + 4 pad)
    constexpr int BSR = 136;   // B packed row stride in u32 (128 + 8 pad)
    __shared__ uint32_t Ahs[2][128][ASR], Als[2][128][ASR];
    __shared__ uint32_t Bhs[2][8][BSR],  Bls[2][8][BSR];

    const int tid  = threadIdx.x;
    const int bm   = blockIdx.y * 128;
    const int bn   = blockIdx.x * 128;
    const int lane = tid & 31, warp = tid >> 5;
    const int wm = (warp >> 1) * 32;
    const int wn = (warp & 1) * 64;
    const int g  = lane >> 2, tg = lane & 3;

    const int ar = tid >> 2, ak = (tid & 3) * 4, akp = (tid & 3) * 2;
    const int bq = tid >> 5, bc = (tid & 31) * 4;   // B: packed row bq (k=2bq,2bq+1)

    float acc[2][8][4];
    #pragma unroll
    for (int im = 0; im < 2; im++)
        #pragma unroll
        for (int jn = 0; jn < 8; jn++)
            #pragma unroll
            for (int q = 0; q < 4; q++) acc[im][jn][q] = 0.f;

    const float* Ap = A + (size_t)bm * lda;
    const float* Bp = B + bn;

    float4 Areg0, Areg1, Breg0, Breg1;

    auto gload = [&](int kt) {
        int k0 = kt * 16;
        Areg0 = *(const float4*)(Ap + (size_t)ar * lda + k0 + ak);
        Areg1 = *(const float4*)(Ap + (size_t)(ar + 64) * lda + k0 + ak);
        Breg0 = *(const float4*)(Bp + (size_t)(k0 + 2 * bq) * ldb + bc);      // k row 2bq
        Breg1 = *(const float4*)(Bp + (size_t)(k0 + 2 * bq + 1) * ldb + bc);  // k row 2bq+1
    };
    auto sstore = [&](int bf) {
        uint32_t h0, l0, h1, l1;
        // A row ar: k pairs (ak,ak+1), (ak+2,ak+3) -> packed cols akp, akp+1
        bf_split_pack(Areg0.x, Areg0.y, h0, l0);
        bf_split_pack(Areg0.z, Areg0.w, h1, l1);
        Ahs[bf][ar][akp] = h0; Ahs[bf][ar][akp + 1] = h1;
        Als[bf][ar][akp] = l0; Als[bf][ar][akp + 1] = l1;
        bf_split_pack(Areg1.x, Areg1.y, h0, l0);
        bf_split_pack(Areg1.z, Areg1.w, h1, l1);
        Ahs[bf][ar + 64][akp] = h0; Ahs[bf][ar + 64][akp + 1] = h1;
        Als[bf][ar + 64][akp] = l0; Als[bf][ar + 64][akp + 1] = l1;
        // B: pack along k: (row 2bq, row 2bq+1) per column
        uint32_t hh[4], ll[4];
        const float* r0 = (const float*)&Breg0;
        const float* r1 = (const float*)&Breg1;
        #pragma unroll
        for (int j = 0; j < 4; j++) bf_split_pack(r0[j], r1[j], hh[j], ll[j]);
        *(uint4*)&Bhs[bf][bq][bc] = *(uint4*)hh;
        *(uint4*)&Bls[bf][bq][bc] = *(uint4*)ll;
    };

    gload(0);
    sstore(0);
    __syncthreads();

    const int nkt = K / 16;
    for (int kt = 0; kt < nkt; kt++) {
        const int bf = kt & 1;
        const bool has_next = (kt + 1 < nkt);
        if (has_next) gload(kt + 1);

        uint32_t ah[2][4], al[2][4];
        #pragma unroll
        for (int im = 0; im < 2; im++) {
            int m = wm + im * 16 + g;
            ah[im][0] = Ahs[bf][m][tg];
            ah[im][1] = Ahs[bf][m + 8][tg];
            ah[im][2] = Ahs[bf][m][tg + 4];
            ah[im][3] = Ahs[bf][m + 8][tg + 4];
            al[im][0] = Als[bf][m][tg];
            al[im][1] = Als[bf][m + 8][tg];
            al[im][2] = Als[bf][m][tg + 4];
            al[im][3] = Als[bf][m + 8][tg + 4];
        }
        #pragma unroll
        for (int jn = 0; jn < 8; jn++) {
            int n = wn + jn * 8 + g;
            uint32_t bh0 = Bhs[bf][tg][n];
            uint32_t bh1 = Bhs[bf][tg + 4][n];
            uint32_t bl0 = Bls[bf][tg][n];
            uint32_t bl1 = Bls[bf][tg + 4][n];
            #pragma unroll
            for (int im = 0; im < 2; im++) {
                mma16(acc[im][jn], ah[im][0], ah[im][1], ah[im][2], ah[im][3], bl0, bl1);
                mma16(acc[im][jn], al[im][0], al[im][1], al[im][2], al[im][3], bh0, bh1);
                mma16(acc[im][jn], ah[im][0], ah[im][1], ah[im][2], ah[im][3], bh0, bh1);
            }
        }

        if (has_next) {
            sstore(bf ^ 1);     // bf^1 reads finished before prior barrier
            __syncthreads();    // publish for next iteration
        }
    }

    #pragma unroll
    for (int im = 0; im < 2; im++) {
        int r0 = bm + wm + im * 16 + g;
        #pragma unroll
        for (int jn = 0; jn < 8; jn++) {
            int c0 = bn + wn + jn * 8 + 2 * tg;
            float v00 = acc[im][jn][0], v01 = acc[im][jn][1];
            float v10 = acc[im][jn][2], v11 = acc[im][jn][3];
            if (EPI == 1 || EPI == 2) {
                float b0 = bias[c0], b1 = bias[c0 + 1];
                v00 += b0; v01 += b1; v10 += b0; v11 += b1;
            }
            if (EPI == 2) {
                v00 = (v00 > 15.f) ? v00 : log1pf(__expf(v00));
                v01 = (v01 > 15.f) ? v01 : log1pf(__expf(v01));
                v10 = (v10 > 15.f) ? v10 : log1pf(__expf(v10));
                v11 = (v11 > 15.f) ? v11 : log1pf(__expf(v11));
            }
            if (EPI == 3) {
                float2 rA = *(const float2*)(res + (size_t)r0 * ldc + c0);
                float2 rB = *(const float2*)(res + (size_t)(r0 + 8) * ldc + c0);
                v00 += rA.x; v01 += rA.y; v10 += rB.x; v11 += rB.y;
            }
            float2 o0 = make_float2(v00, v01);
            float2 o1 = make_float2(v10, v11);
            *(float2*)(C + (size_t)r0 * ldc + c0) = o0;
            *(float2*)(C + (size_t)(r0 + 8) * ldc + c0) = o1;
        }
    }
}

static void launch_gemm(int epi, int M, int N, int K,
                        const float* A, int lda, const float* B, int ldb,
                        float* C, int ldc, const float* bias, const float* res,
                        cudaStream_t st)
{
    dim3 grid(N / 128, M / 128);
    switch (epi) {
        case 0: tgemm_k<0><<<grid, 256, 0, st>>>(M, N, K, A, lda, B, ldb, C, ldc, bias, res); break;
        case 1: tgemm_k<1><<<grid, 256, 0, st>>>(M, N, K, A, lda, B, ldb, C, ldc, bias, res); break;
        case 2: tgemm_k<2><<<grid, 256, 0, st>>>(M, N, K, A, lda, B, ldb, C, ldc, bias, res); break;
        default: tgemm_k<3><<<grid, 256, 0, st>>>(M, N, K, A, lda, B, ldb, C, ldc, bias, res); break;
    }
}

// ---------------- split-K GEMM for Wx: [2048 x 96] = xc[2048x2048] @ Wx ----------------
__global__ __launch_bounds__(256)
void sgemm96_splitk_k(const float* __restrict__ A, int lda, int K,
                      const float* __restrict__ B,
                      float* __restrict__ Cp)
{
    __shared__ float As[16][132];
    __shared__ float Bs[16][96];
    const int tid = threadIdx.x;
    const int split = blockIdx.x;
    const int bm = blockIdx.y * 128;
    const int kchunk = K / cWXS;
    const int kbase = split * kchunk;
    const int tx = tid & 15, ty = tid >> 4;
    const int ar0 = tid >> 2, ak0 = (tid & 3) * 4;
    const int brow = tid >> 4, bcb = (tid & 15) * 6;

    float acc[8][6];
    #pragma unroll
    for (int i = 0; i < 8; i++)
        #pragma unroll
        for (int j = 0; j < 6; j++) acc[i][j] = 0.f;

    for (int k0 = 0; k0 < kchunk; k0 += 16) {
        int kg = kbase + k0;
        float4 a0 = *(const float4*)(A + (size_t)(bm + ar0) * lda + kg + ak0);
        float4 a1 = *(const float4*)(A + (size_t)(bm + ar0 + 64) * lda + kg + ak0);
        As[ak0 + 0][ar0] = a0.x; As[ak0 + 1][ar0] = a0.y;
        As[ak0 + 2][ar0] = a0.z; As[ak0 + 3][ar0] = a0.w;
        As[ak0 + 0][ar0 + 64] = a1.x; As[ak0 + 1][ar0 + 64] = a1.y;
        As[ak0 + 2][ar0 + 64] = a1.z; As[ak0 + 3][ar0 + 64] = a1.w;
        #pragma unroll
        for (int j = 0; j < 6; j++)
            Bs[brow][bcb + j] = B[(size_t)(kg + brow) * 96 + bcb + j];
        __syncthreads();
        #pragma unroll
        for (int kk = 0; kk < 16; kk++) {
            float ra[8], rb[6];
            *(float4*)&ra[0] = *(const float4*)&As[kk][ty * 8];
            *(float4*)&ra[4] = *(const float4*)&As[kk][ty * 8 + 4];
            #pragma unroll
            for (int j = 0; j < 6; j++) rb[j] = Bs[kk][tx * 6 + j];
            #pragma unroll
            for (int i = 0; i < 8; i++)
                #pragma unroll
                for (int j = 0; j < 6; j++) acc[i][j] += ra[i] * rb[j];
        }
        __syncthreads();
    }
    float* out = Cp + (size_t)split * cBL * 96;
    #pragma unroll
    for (int i = 0; i < 8; i++) {
        int r = bm + ty * 8 + i;
        #pragma unroll
        for (int j = 0; j < 6; j++)
            out[(size_t)r * 96 + tx * 6 + j] = acc[i][j];
    }
}

__global__ void reduce96_k(const float* __restrict__ Cp, float* __restrict__ C) {
    int i = blockIdx.x * 256 + threadIdx.x;
    float s = 0.f;
    #pragma unroll
    for (int p = 0; p < cWXS; p++) s += Cp[(size_t)p * cBL * 96 + i];
    C[i] = s;
}

// ---------------- copy x -> three branch states ----------------
__global__ void copy3_k(const float* __restrict__ x, float* a, float* b, float* c) {
    int i = blockIdx.x * 256 + threadIdx.x;
    float4 v = ((const float4*)x)[i];
    ((float4*)a)[i] = v;
    ((float4*)b)[i] = v;
    ((float4*)c)[i] = v;
}

// ---------------- RMSNorm ----------------
__global__ void rmsnorm_k(const float* __restrict__ x, const float* __restrict__ w,
                          float* __restrict__ o)
{
    __shared__ float sm[8];
    int row = blockIdx.x, tid = threadIdx.x;
    float4 v = ((const float4*)(x + (size_t)row * cD))[tid];
    float ss = v.x * v.x + v.y * v.y + v.z * v.z + v.w * v.w;
    float tot = block_sum256(ss, sm);
    float sc = rsqrtf(tot * (1.f / cD) + 1e-6f);
    float4 wv = ((const float4*)w)[tid];
    float4 r;
    r.x = v.x * sc * wv.x; r.y = v.y * sc * wv.y;
    r.z = v.z * sc * wv.z; r.w = v.w * sc * wv.w;
    ((float4*)(o + (size_t)row * cD))[tid] = r;
}

// ---------------- mamba: depthwise conv + silu ----------------
__global__ void conv_silu_k(const float* __restrict__ xz, const float* __restrict__ cw,
                            const float* __restrict__ cb, float* __restrict__ xc)
{
    int idx = blockIdx.x * 256 + threadIdx.x;
    int c = idx & (cDI - 1);
    int t = (idx >> 11) & (cL - 1);
    int b = idx >> 21;
    float acc = cb[c];
    #pragma unroll
    for (int j = 0; j < 4; j++) {
        int tt = t + j - 3;
        if (tt >= 0)
            acc += xz[((size_t)(b * cL + tt)) * (2 * cDI) + c] * cw[j * cDI + c];
    }
    xc[idx] = acc * sigmoid_f(acc);
}

// ---------------- mamba selective scan: 8-step unroll + depth-2 pipeline ----------------
__global__ void mamba_scan_k(const float* __restrict__ delta, const float* __restrict__ xc,
                             const float* __restrict__ xdbl, const float* __restrict__ xz,
                             const float* __restrict__ Alog, const float* __restrict__ Dp,
                             float* __restrict__ y)
{
    int warp = (blockIdx.x * blockDim.x + threadIdx.x) >> 5;
    int lane = threadIdx.x & 31;
    int s = lane & 15;
    int half = lane >> 4;
    int g = warp * 2 + half;
    int b = g >> 11;
    int d = g & (cDI - 1);

    float A  = -__expf(Alog[d * cDS + s]);
    float Dd = Dp[d];
    float h = 0.f;

    float dl0[cU], u0[cU], Bv0[cU], Cv0[cU], z0[cU];
    float dl1[cU], u1[cU], Bv1[cU], Cv1[cU], z1[cU];

    #pragma unroll
    for (int j = 0; j < cU; j++) {
        int row = b * cL + j;
        dl0[j] = delta[(size_t)row * cDI + d];
        u0[j]  = xc[(size_t)row * cDI + d];
        Bv0[j] = xdbl[(size_t)row * cXDB + cDTR + s];
        Cv0[j] = xdbl[(size_t)row * cXDB + cDTR + cDS + s];
        z0[j]  = xz[(size_t)row * (2 * cDI) + cDI + d];
    }

    for (int t0 = 0; t0 < cL; t0 += cU) {
        const bool nxt = (t0 + cU < cL);
        if (nxt) {
            #pragma unroll
            for (int j = 0; j < cU; j++) {
                int row = b * cL + t0 + cU + j;
                dl1[j] = delta[(size_t)row * cDI + d];
                u1[j]  = xc[(size_t)row * cDI + d];
                Bv1[j] = xdbl[(size_t)row * cXDB + cDTR + s];
                Cv1[j] = xdbl[(size_t)row * cXDB + cDTR + cDS + s];
                z1[j]  = xz[(size_t)row * (2 * cDI) + cDI + d];
            }
        }
        #pragma unroll
        for (int j = 0; j < cU; j++) {
            float dA = __expf(dl0[j] * A);
            h = h * dA + dl0[j] * u0[j] * Bv0[j];
            float p = h * Cv0[j];
            p += __shfl_xor_sync(0xffffffffu, p, 8);
            p += __shfl_xor_sync(0xffffffffu, p, 4);
            p += __shfl_xor_sync(0xffffffffu, p, 2);
            p += __shfl_xor_sync(0xffffffffu, p, 1);
            if (s == 0) {
                float z = z0[j];
                y[(size_t)(b * cL + t0 + j) * cDI + d] = (p + Dd * u0[j]) * (z * sigmoid_f(z));
            }
        }
        if (nxt) {
            #pragma unroll
            for (int j = 0; j < cU; j++) {
                dl0[j] = dl1[j]; u0[j] = u1[j];
                Bv0[j] = Bv1[j]; Cv0[j] = Cv1[j]; z0[j] = z1[j];
            }
        }
    }
}

// ---------------- RWKV: rmsnorm + token-shift mixes ----------------
__global__ void rwkv_mix_k(const float* __restrict__ x, const float* __restrict__ norm,
                           const float* __restrict__ mu,
                           float* __restrict__ mr, float* __restrict__ mk, float* __restrict__ mv)
{
    __shared__ float sm[8];
    int row = blockIdx.x, tid = threadIdx.x;
    int t = row & (cL - 1);
    float4 vc = ((const float4*)(x + (size_t)row * cD))[tid];
    float4 vp = make_float4(0.f, 0.f, 0.f, 0.f);
    if (t > 0) vp = ((const float4*)(x + (size_t)(row - 1) * cD))[tid];
    float ssc = vc.x * vc.x + vc.y * vc.y + vc.z * vc.z + vc.w * vc.w;
    float ssp = vp.x * vp.x + vp.y * vp.y + vp.z * vp.z + vp.w * vp.w;
    float totc = block_sum256(ssc, sm);
    float totp = block_sum256(ssp, sm);
    float sc = rsqrtf(totc * (1.f / cD) + 1e-6f);
    float sp = rsqrtf(totp * (1.f / cD) + 1e-6f);
    float4 wv = ((const float4*)norm)[tid];
    float xn[4] = { vc.x * sc * wv.x, vc.y * sc * wv.y, vc.z * sc * wv.z, vc.w * sc * wv.w };
    float xs[4] = { vp.x * sp * wv.x, vp.y * sp * wv.y, vp.z * sp * wv.z, vp.w * sp * wv.w };
    float* outs[3] = { mr, mk, mv };
    #pragma unroll
    for (int j = 0; j < 3; j++) {
        float4 m4 = ((const float4*)(mu + j * cD))[tid];
        float mm[4] = { m4.x, m4.y, m4.z, m4.w };
        float4 r;
        r.x = xn[0] * mm[0] + xs[0] * (1.f - mm[0]);
        r.y = xn[1] * mm[1] + xs[1] * (1.f - mm[1]);
        r.z = xn[2] * mm[2] + xs[2] * (1.f - mm[2]);
        r.w = xn[3] * mm[3] + xs[3] * (1.f - mm[3]);
        ((float4*)(outs[j] + (size_t)row * cD))[tid] = r;
    }
}

// ---------------- RWKV scan: shuffle reduction + 4-deep smem ring prefetch ----------------
__global__ __launch_bounds__(512)
void rwkv_scan_k(const float* __restrict__ r, const float* __restrict__ k,
                 const float* __restrict__ v, const float* __restrict__ wlog,
                 const float* __restrict__ u, float* __restrict__ y)
{
    int b = blockIdx.x >> 4;
    int h = blockIdx.x & 15;
    int tid = threadIdx.x;
    int vv = tid >> 3;     // 0..63
    int kq = tid & 7;      // 0..7

    __shared__ float sr[4][64], sk[4][64], sv[4][64];

    float wreg[8], ureg[8], S[8];
    #pragma unroll
    for (int i = 0; i < 8; i++) {
        wreg[i] = __expf(-__expf(wlog[h * cDHR + kq * 8 + i]));
        ureg[i] = u[h * cDHR + kq * 8 + i];
        S[i] = 0.f;
    }

    #pragma unroll
    for (int t = 0; t < 3; t++) {
        size_t base = ((size_t)(b * cL + t)) * cD + h * cDHR;
        if (tid < 64)       sr[t][tid]       = r[base + tid];
        else if (tid < 128) sk[t][tid - 64]  = k[base + tid - 64];
        else if (tid < 192) sv[t][tid - 128] = v[base + tid - 128];
    }
    __syncthreads();

    for (int t = 0; t < cL; t++) {
        int cur = t & 3, nb = (t + 3) & 3;

        float pr = 0.f, pk = 0.f, pv = 0.f;
        const bool pf = (t + 3 < cL);
        if (pf) {
            size_t base = ((size_t)(b * cL + t + 3)) * cD + h * cDHR;
            if (tid < 64)       pr = r[base + tid];
            else if (tid < 128) pk = k[base + tid - 64];
            else if (tid < 192) pv = v[base + tid - 128];
        }

        float vt = sv[cur][vv];
        float4 k0 = *(const float4*)&sk[cur][kq * 8];
        float4 k1 = *(const float4*)&sk[cur][kq * 8 + 4];
        float4 r0 = *(const float4*)&sr[cur][kq * 8];
        float4 r1 = *(const float4*)&sr[cur][kq * 8 + 4];
        float kkv[8] = { k0.x, k0.y, k0.z, k0.w, k1.x, k1.y, k1.z, k1.w };
        float rrv[8] = { r0.x, r0.y, r0.z, r0.w, r1.x, r1.y, r1.z, r1.w };
        float yp = 0.f;
        #pragma unroll
        for (int i = 0; i < 8; i++) {
            float kvv = kkv[i] * vt;
            yp += rrv[i] * (S[i] + ureg[i] * kvv);
            S[i] = wreg[i] * S[i] + kvv;
        }
        yp += __shfl_xor_sync(0xffffffffu, yp, 1);
        yp += __shfl_xor_sync(0xffffffffu, yp, 2);
        yp += __shfl_xor_sync(0xffffffffu, yp, 4);
        if (kq == 0)
            y[((size_t)(b * cL + t)) * cD + h * cDHR + vv] = yp;

        __syncthreads();

        if (pf) {
            if (tid < 64)       sr[nb][tid]       = pr;
            else if (tid < 128) sk[nb][tid - 64]  = pk;
            else if (tid < 192) sv[nb][tid - 128] = pv;
        }
    }
}

// ---------------- MHA: one-pass online-softmax attention ----------------
__global__ __launch_bounds__(256)
void mha_flash_k(const float* __restrict__ q, const float* __restrict__ k,
                 const float* __restrict__ v, float* __restrict__ o)
{
    __shared__ float skm[64][32];
    __shared__ float svm[64][32];
    int b = blockIdx.z, h = blockIdx.y, qc = blockIdx.x;
    int tid = threadIdx.x;
    int t = qc * 256 + tid;
    size_t qbase = ((size_t)(b * cL + t) * cHA + h) * cDHA;

    float qr[32], oacc[32];
    #pragma unroll
    for (int d = 0; d < 32; d += 4) *(float4*)&qr[d] = *(const float4*)(q + qbase + d);
    #pragma unroll
    for (int d = 0; d < 32; d++) oacc[d] = 0.f;
    float m = -1e30f, l = 0.f;
    const float scale = 0.17677669529663687f;

    for (int t0 = 0; t0 < cL; t0 += 64) {
        int rr = tid >> 2, cc = (tid & 3) * 8;
        size_t kb = ((size_t)(b * cL + t0 + rr) * cHA + h) * cDHA + cc;
        *(float4*)&skm[rr][cc]     = *(const float4*)(k + kb);
        *(float4*)&skm[rr][cc + 4] = *(const float4*)(k + kb + 4);
        *(float4*)&svm[rr][cc]     = *(const float4*)(v + kb);
        *(float4*)&svm[rr][cc + 4] = *(const float4*)(v + kb + 4);
        __syncthreads();
        #pragma unroll 2
        for (int j = 0; j < 64; j++) {
            float s = 0.f;
            #pragma unroll
            for (int d = 0; d < 32; d += 4) {
                float4 kk4 = *(const float4*)&skm[j][d];
                s += qr[d] * kk4.x + qr[d + 1] * kk4.y + qr[d + 2] * kk4.z + qr[d + 3] * kk4.w;
            }
            s *= scale;
            float mn = fmaxf(m, s);
            float corr = __expf(m - mn);
            float p = __expf(s - mn);
            l = l * corr + p;
            m = mn;
            #pragma unroll
            for (int d = 0; d < 32; d += 4) {
                float4 vv4 = *(const float4*)&svm[j][d];
                oacc[d]     = oacc[d]     * corr + p * vv4.x;
                oacc[d + 1] = oacc[d + 1] * corr + p * vv4.y;
                oacc[d + 2] = oacc[d + 2] * corr + p * vv4.z;
                oacc[d + 3] = oacc[d + 3] * corr + p * vv4.w;
            }
        }
        __syncthreads();
    }
    float inv = 1.f / l;
    #pragma unroll
    for (int d = 0; d < 32; d += 4) {
        float4 r4 = make_float4(oacc[d] * inv, oacc[d + 1] * inv,
                                oacc[d + 2] * inv, oacc[d + 3] * inv);
        *(float4*)(o + qbase + d) = r4;
    }
}

// ---------------- final: concat -> linear(3) -> softmax ----------------
__global__ void final_k(const float* __restrict__ mx, const float* __restrict__ rx,
                        const float* __restrict__ tx, const float* __restrict__ fW,
                        const float* __restrict__ fb, float* __restrict__ out)
{
    int row = blockIdx.x, tid = threadIdx.x;
    float a0 = 0.f, a1 = 0.f, a2 = 0.f;
    const float* xs[3] = { mx, rx, tx };
    for (int p = 0; p < 3; p++) {
        const float* xp = xs[p] + (size_t)row * cD;
        const float* wp = fW + (size_t)p * cD * 3;
        for (int i = tid; i < cD; i += 128) {
            float vv = xp[i];
            a0 += vv * wp[i * 3 + 0];
            a1 += vv * wp[i * 3 + 1];
            a2 += vv * wp[i * 3 + 2];
        }
    }
    #pragma unroll
    for (int mk = 16; mk; mk >>= 1) {
        a0 += __shfl_xor_sync(0xffffffffu, a0, mk);
        a1 += __shfl_xor_sync(0xffffffffu, a1, mk);
        a2 += __shfl_xor_sync(0xffffffffu, a2, mk);
    }
    __shared__ float s0[4], s1[4], s2[4];
    int w = tid >> 5;
    if ((tid & 31) == 0) { s0[w] = a0; s1[w] = a1; s2[w] = a2; }
    __syncthreads();
    if (tid == 0) {
        float b0 = s0[0] + s0[1] + s0[2] + s0[3] + fb[0];
        float b1 = s1[0] + s1[1] + s1[2] + s1[3] + fb[1];
        float b2 = s2[0] + s2[1] + s2[2] + s2[3] + fb[2];
        float mm = fmaxf(b0, fmaxf(b1, b2));
        float e0 = __expf(b0 - mm), e1 = __expf(b1 - mm), e2 = __expf(b2 - mm);
        float inv = 1.f / (e0 + e1 + e2);
        out[row * 3 + 0] = e0 * inv;
        out[row * 3 + 1] = e1 * inv;
        out[row * 3 + 2] = e2 * inv;
    }
}

// ---------------- persistent stream/event resources ----------------
static cudaStream_t g_s1 = nullptr;
static cudaStream_t g_s2 = nullptr;
static cudaEvent_t  g_eF = nullptr;
static cudaEvent_t  g_e1 = nullptr;
static cudaEvent_t  g_e2 = nullptr;

// ---------------- host orchestration ----------------
extern "C" void kernel_launch(void* const* d_in, const int* in_sizes, int n_in,
                              void* d_out, int out_size)
{
    (void)in_sizes; (void)n_in; (void)out_size;
    const float* x       = (const float*)d_in[0];
    const float* m_norm  = (const float*)d_in[1];
    const float* m_Win   = (const float*)d_in[2];
    const float* m_convw = (const float*)d_in[3];
    const float* m_convb = (const float*)d_in[4];
    const float* m_Wx    = (const float*)d_in[5];
    const float* m_Wdt   = (const float*)d_in[6];
    const float* m_bdt   = (const float*)d_in[7];
    const float* m_Alog  = (const float*)d_in[8];
    const float* m_D     = (const float*)d_in[9];
    const float* m_Wout  = (const float*)d_in[10];
    const float* r_norm  = (const float*)d_in[11];
    const float* r_mu    = (const float*)d_in[12];
    const float* r_Wr    = (const float*)d_in[13];
    const float* r_Wk    = (const float*)d_in[14];
    const float* r_Wv    = (const float*)d_in[15];
    const float* r_Wo    = (const float*)d_in[16];
    const float* r_wlog  = (const float*)d_in[17];
    const float* r_u     = (const float*)d_in[18];
    const float* a_Wq    = (const float*)d_in[19];
    const float* a_bq    = (const float*)d_in[20];
    const float* a_Wk    = (const float*)d_in[21];
    const float* a_bk    = (const float*)d_in[22];
    const float* a_Wv    = (const float*)d_in[23];
    const float* a_bv    = (const float*)d_in[24];
    const float* a_Wo    = (const float*)d_in[25];
    const float* a_bo    = (const float*)d_in[26];
    const float* f_W     = (const float*)d_in[27];
    const float* f_b     = (const float*)d_in[28];
    float* out = (float*)d_out;

    float *p_mx, *p_rx, *p_tx, *p_xn, *p_xz, *p_xc, *p_xdbl, *p_wxp, *p_delta, *p_ym;
    float *p_ar, *p_ak, *p_av, *p_br, *p_bk, *p_bv, *p_y1;
    float *p_tq, *p_tk, *p_tv, *p_to;
    cudaGetSymbolAddress((void**)&p_mx, g_mx);
    cudaGetSymbolAddress((void**)&p_rx, g_rx);
    cudaGetSymbolAddress((void**)&p_tx, g_tx);
    cudaGetSymbolAddress((void**)&p_xn, g_xn);
    cudaGetSymbolAddress((void**)&p_xz, g_xz);
    cudaGetSymbolAddress((void**)&p_xc, g_xc);
    cudaGetSymbolAddress((void**)&p_xdbl, g_xdbl);
    cudaGetSymbolAddress((void**)&p_wxp, g_wxp);
    cudaGetSymbolAddress((void**)&p_delta, g_delta);
    cudaGetSymbolAddress((void**)&p_ym, g_ym);
    cudaGetSymbolAddress((void**)&p_ar, g_ar);
    cudaGetSymbolAddress((void**)&p_ak, g_ak);
    cudaGetSymbolAddress((void**)&p_av, g_av);
    cudaGetSymbolAddress((void**)&p_br, g_br);
    cudaGetSymbolAddress((void**)&p_bk, g_bk);
    cudaGetSymbolAddress((void**)&p_bv, g_bv);
    cudaGetSymbolAddress((void**)&p_y1, g_y1);
    cudaGetSymbolAddress((void**)&p_tq, g_tq);
    cudaGetSymbolAddress((void**)&p_tk, g_tk);
    cudaGetSymbolAddress((void**)&p_tv, g_tv);
    cudaGetSymbolAddress((void**)&p_to, g_to);

    if (g_s1 == nullptr) {
        cudaStreamCreateWithFlags(&g_s1, cudaStreamNonBlocking);
        cudaStreamCreateWithFlags(&g_s2, cudaStreamNonBlocking);
        cudaEventCreateWithFlags(&g_eF, cudaEventDisableTiming);
        cudaEventCreateWithFlags(&g_e1, cudaEventDisableTiming);
        cudaEventCreateWithFlags(&g_e2, cudaEventDisableTiming);
    }
    cudaStream_t s0 = 0, s1 = g_s1, s2 = g_s2;

    copy3_k<<<(cBL * cD) / 4 / 256, 256, 0, s0>>>(x, p_mx, p_rx, p_tx);

    // fork
    cudaEventRecord(g_eF, s0);
    cudaStreamWaitEvent(s1, g_eF, 0);
    cudaStreamWaitEvent(s2, g_eF, 0);

    // ---- Mamba chain (s0) ----
    for (int i = 0; i < cNM; i++) {
        rmsnorm_k<<<cBL, 256, 0, s0>>>(p_mx, m_norm + i * cD, p_xn);
        launch_gemm(0, cBL, 2 * cDI, cD, p_xn, cD,
                    m_Win + (size_t)i * cD * 2 * cDI, 2 * cDI, p_xz, 2 * cDI,
                    nullptr, nullptr, s0);
        conv_silu_k<<<(cBL * cDI) / 256, 256, 0, s0>>>(p_xz, m_convw + i * 4 * cDI,
                                                       m_convb + i * cDI, p_xc);
        sgemm96_splitk_k<<<dim3(cWXS, cBL / 128), 256, 0, s0>>>(
            p_xc, cDI, cDI, m_Wx + (size_t)i * cDI * cXDB, p_wxp);
        reduce96_k<<<(cBL * cXDB) / 256, 256, 0, s0>>>(p_wxp, p_xdbl);
        launch_gemm(2, cBL, cDI, cDTR, p_xdbl, cXDB,
                    m_Wdt + (size_t)i * cDTR * cDI, cDI, p_delta, cDI,
                    m_bdt + i * cDI, nullptr, s0);
        mamba_scan_k<<<(cB * cDI / 2) / 8, 256, 0, s0>>>(p_delta, p_xc, p_xdbl, p_xz,
                                                         m_Alog + (size_t)i * cDI * cDS,
                                                         m_D + i * cDI, p_ym);
        launch_gemm(3, cBL, cD, cDI, p_ym, cDI,
                    m_Wout + (size_t)i * cDI * cD, cD, p_mx, cD, nullptr, p_mx, s0);
    }

    // ---- RWKV chain (s1) ----
    for (int i = 0; i < cNR; i++) {
        rwkv_mix_k<<<cBL, 256, 0, s1>>>(p_rx, r_norm + i * cD,
                                        r_mu + (size_t)i * 3 * cD, p_ar, p_ak, p_av);
        launch_gemm(0, cBL, cD, cD, p_ar, cD, r_Wr + (size_t)i * cD * cD, cD,
                    p_br, cD, nullptr, nullptr, s1);
        launch_gemm(0, cBL, cD, cD, p_ak, cD, r_Wk + (size_t)i * cD * cD, cD,
                    p_bk, cD, nullptr, nullptr, s1);
        launch_gemm(0, cBL, cD, cD, p_av, cD, r_Wv + (size_t)i * cD * cD, cD,
                    p_bv, cD, nullptr, nullptr, s1);
        rwkv_scan_k<<<cB * cHR, 512, 0, s1>>>(p_br, p_bk, p_bv,
                                              r_wlog + (size_t)i * cHR * cDHR,
                                              r_u + (size_t)i * cHR * cDHR, p_y1);
        launch_gemm(3, cBL, cD, cD, p_y1, cD, r_Wo + (size_t)i * cD * cD, cD,
                    p_rx, cD, nullptr, p_rx, s1);
    }

    // ---- MHA chain (s2) ----
    for (int i = 0; i < cNT; i++) {
        launch_gemm(1, cBL, cD, cD, p_tx, cD, a_Wq + (size_t)i * cD * cD, cD,
                    p_tq, cD, a_bq + i * cD, nullptr, s2);
        launch_gemm(1, cBL, cD, cD, p_tx, cD, a_Wk + (size_t)i * cD * cD, cD,
                    p_tk, cD, a_bk + i * cD, nullptr, s2);
        launch_gemm(1, cBL, cD, cD, p_tx, cD, a_Wv + (size_t)i * cD * cD, cD,
                    p_tv, cD, a_bv + i * cD, nullptr, s2);
        mha_flash_k<<<dim3(4, cHA, cB), 256, 0, s2>>>(p_tq, p_tk, p_tv, p_to);
        launch_gemm(1, cBL, cD, cD, p_to, cD, a_Wo + (size_t)i * cD * cD, cD,
                    p_tx, cD, a_bo + i * cD, nullptr, s2);
    }

    // join
    cudaEventRecord(g_e1, s1);
    cudaEventRecord(g_e2, s2);
    cudaStreamWaitEvent(s0, g_e1, 0);
    cudaStreamWaitEvent(s0, g_e2, 0);

    final_k<<<cBL, 128, 0, s0>>>(p_mx, p_rx, p_tx, f_W, f_b, out);
}